// round 13
// baseline (speedup 1.0000x reference)
#include <cuda_runtime.h>
#include <cuda_fp16.h>
#include <cstdint>

#define BATCH 32768
#define HD 128
#define OD 32
#define DEPTH 5
typedef uint32_t u32;

// ---- weight tile offsets in g_wt (halves) ----
#define W_ANC_WH  0
#define W_FRAT_WH 98304
#define W_ANC_WI  196608
#define W_FRAT_WI 221184
#define W_UF      245760
#define W_UA      278528
#define W_H2O     311296
__device__ __half g_wt[319488];

__device__ __half g_hAh[DEPTH + 1][BATCH * HD];
__device__ __half g_hAl[DEPTH + 1][BATCH * HD];
__device__ __half g_prh[DEPTH + 1][BATCH * OD];
__device__ __half g_prl[DEPTH + 1][BATCH * OD];

// ===================== helpers =====================
__device__ __forceinline__ u32 smaddr(const void* p) {
    u32 a;
    asm("{ .reg .u64 t; cvta.to.shared.u64 t, %1; cvt.u32.u64 %0, t; }" : "=r"(a) : "l"(p));
    return a;
}
__device__ __forceinline__ void cpa16(u32 d, const void* s) {
    asm volatile("cp.async.cg.shared.global [%0], [%1], 16;" :: "r"(d), "l"(s) : "memory");
}
__device__ __forceinline__ void cpcommit() {
    asm volatile("cp.async.commit_group;" ::: "memory");
}
__device__ __forceinline__ void cpwait0() {
    asm volatile("cp.async.wait_group 0;" ::: "memory");
}
__device__ __forceinline__ void ldm4(u32* r, u32 a) {
    asm volatile("ldmatrix.sync.aligned.m8n8.x4.shared.b16 {%0,%1,%2,%3}, [%4];"
                 : "=r"(r[0]), "=r"(r[1]), "=r"(r[2]), "=r"(r[3]) : "r"(a));
}
__device__ __forceinline__ void mmaf(float* c, const u32* a, const u32* b) {
    asm volatile(
        "mma.sync.aligned.m16n8k16.row.col.f32.f16.f16.f32 "
        "{%0,%1,%2,%3},{%4,%5,%6,%7},{%8,%9},{%0,%1,%2,%3};"
        : "+f"(c[0]), "+f"(c[1]), "+f"(c[2]), "+f"(c[3])
        : "r"(a[0]), "r"(a[1]), "r"(a[2]), "r"(a[3]), "r"(b[0]), "r"(b[1]));
}
__device__ __forceinline__ float fsig(float x)  { return __fdividef(1.0f, 1.0f + __expf(-x)); }
__device__ __forceinline__ float ftanh(float x) { float u = __expf(2.0f * x); return 1.0f - __fdividef(2.0f, u + 1.0f); }
__device__ __forceinline__ void wsplit(float v, __half& h, __half& l) {
    h = __float2half_rn(v);
    l = __float2half_rn(v - __half2float(h));
}

// ---- ldmatrix addressing ----
__device__ __forceinline__ void ldmA128(u32* r, u32 base, int m0, int lane, int kc) {
    int row = m0 + (lane & 15), c16 = 2 * kc + (lane >> 4);
    ldm4(r, base + (u32)row * 256u + (u32)((c16 ^ (row & 7)) << 4));
}
__device__ __forceinline__ void ldmBh(u32* r, u32 base, int n0, int lane, int kc) {
    int row = n0 + (lane & 7) + ((lane >> 4) << 3), c8 = 2 * kc + ((lane >> 3) & 1);
    ldm4(r, base + (u32)row * 128u + (u32)((c8 ^ (row & 7)) << 4));
}
__device__ __forceinline__ void ldmA32(u32* r, u32 base, int m0, int lane, int kc) {
    int row = m0 + (lane & 15), c4 = 2 * kc + (lane >> 4);
    ldm4(r, base + (u32)row * 64u + (u32)((c4 ^ (row & 3)) << 4));
}
__device__ __forceinline__ void ldmB32(u32* r, u32 base, int n0, int lane, int kc) {
    int row = n0 + (lane & 7) + ((lane >> 4) << 3), c4 = 2 * kc + ((lane >> 3) & 1);
    ldm4(r, base + (u32)row * 64u + (u32)((c4 ^ (row & 3)) << 4));
}

// ---- 24 MMAs issued term-major over 8 independent accumulators ----
__device__ __forceinline__ void issue24(float (*acc)[4], const u32 a[4][4],
                                        const u32 bh[2][4], const u32 bl[2][4]) {
#pragma unroll
    for (int G = 0; G < 2; G++)
#pragma unroll
        for (int mf = 0; mf < 2; mf++) {
            mmaf(acc[mf * 4 + G * 2],     a[mf], bh[G]);
            mmaf(acc[mf * 4 + G * 2 + 1], a[mf], bh[G] + 2);
        }
#pragma unroll
    for (int G = 0; G < 2; G++)
#pragma unroll
        for (int mf = 0; mf < 2; mf++) {
            mmaf(acc[mf * 4 + G * 2],     a[mf], bl[G]);
            mmaf(acc[mf * 4 + G * 2 + 1], a[mf], bl[G] + 2);
        }
#pragma unroll
    for (int G = 0; G < 2; G++)
#pragma unroll
        for (int mf = 0; mf < 2; mf++) {
            mmaf(acc[mf * 4 + G * 2],     a[2 + mf], bh[G]);
            mmaf(acc[mf * 4 + G * 2 + 1], a[2 + mf], bh[G] + 2);
        }
}

// ---- single-gate 32x32 kstep (B from half-K panel: hi at BH, lo at BL) ----
__device__ __forceinline__ void kstep128h(float (*acc)[4], u32 AH, u32 AL, u32 BH, u32 BL,
                                          int m0, int n0, int lane, int kcA, int kcB) {
    u32 a[4][4];
    ldmA128(a[0], AH, m0, lane, kcA);      ldmA128(a[1], AH, m0 + 16, lane, kcA);
    ldmA128(a[2], AL, m0, lane, kcA);      ldmA128(a[3], AL, m0 + 16, lane, kcA);
    u32 bh[2][4], bl[2][4];
    ldmBh(bh[0], BH, n0, lane, kcB);       ldmBh(bh[1], BH, n0 + 16, lane, kcB);
    ldmBh(bl[0], BL, n0, lane, kcB);       ldmBh(bl[1], BL, n0 + 16, lane, kcB);
    issue24(acc, a, bh, bl);
}
__device__ __forceinline__ void kstep32w(float (*acc)[4], u32 AH, u32 AL, u32 BH, u32 BL,
                                         int m0, int n0, int lane, int kc) {
    u32 a[4][4];
    ldmA32(a[0], AH, m0, lane, kc);      ldmA32(a[1], AH, m0 + 16, lane, kc);
    ldmA32(a[2], AL, m0, lane, kc);      ldmA32(a[3], AL, m0 + 16, lane, kc);
    u32 bh[2][4], bl[2][4];
    ldmB32(bh[0], BH, n0, lane, kc);     ldmB32(bh[1], BH, n0 + 16, lane, kc);
    ldmB32(bl[0], BL, n0, lane, kc);     ldmB32(bl[1], BL, n0 + 16, lane, kc);
    issue24(acc, a, bh, bl);
}
// ---- dual-gate ksteps: A loaded once, feeds gate-r then gate-z accumulators ----
__device__ __forceinline__ void kdual128(float (*aR)[4], float (*aZ)[4], u32 AH, u32 AL,
                                         u32 BRh, u32 BRl, u32 BZh, u32 BZl,
                                         int m0, int n0, int lane, int kcA, int kcB) {
    u32 a[4][4];
    ldmA128(a[0], AH, m0, lane, kcA);      ldmA128(a[1], AH, m0 + 16, lane, kcA);
    ldmA128(a[2], AL, m0, lane, kcA);      ldmA128(a[3], AL, m0 + 16, lane, kcA);
    {
        u32 bh[2][4], bl[2][4];
        ldmBh(bh[0], BRh, n0, lane, kcB);  ldmBh(bh[1], BRh, n0 + 16, lane, kcB);
        ldmBh(bl[0], BRl, n0, lane, kcB);  ldmBh(bl[1], BRl, n0 + 16, lane, kcB);
        issue24(aR, a, bh, bl);
    }
    {
        u32 bh[2][4], bl[2][4];
        ldmBh(bh[0], BZh, n0, lane, kcB);  ldmBh(bh[1], BZh, n0 + 16, lane, kcB);
        ldmBh(bl[0], BZl, n0, lane, kcB);  ldmBh(bl[1], BZl, n0 + 16, lane, kcB);
        issue24(aZ, a, bh, bl);
    }
}
__device__ __forceinline__ void kdual32(float (*aR)[4], float (*aZ)[4], u32 AH, u32 AL,
                                        u32 BRh, u32 BRl, u32 BZh, u32 BZl,
                                        int m0, int n0, int lane, int kc) {
    u32 a[4][4];
    ldmA32(a[0], AH, m0, lane, kc);      ldmA32(a[1], AH, m0 + 16, lane, kc);
    ldmA32(a[2], AL, m0, lane, kc);      ldmA32(a[3], AL, m0 + 16, lane, kc);
    {
        u32 bh[2][4], bl[2][4];
        ldmB32(bh[0], BRh, n0, lane, kc);  ldmB32(bh[1], BRh, n0 + 16, lane, kc);
        ldmB32(bl[0], BRl, n0, lane, kc);  ldmB32(bl[1], BRl, n0 + 16, lane, kc);
        issue24(aR, a, bh, bl);
    }
    {
        u32 bh[2][4], bl[2][4];
        ldmB32(bh[0], BZh, n0, lane, kc);  ldmB32(bh[1], BZh, n0 + 16, lane, kc);
        ldmB32(bl[0], BZl, n0, lane, kc);  ldmB32(bl[1], BZl, n0 + 16, lane, kc);
        issue24(aZ, a, bh, bl);
    }
}
__device__ __forceinline__ void zacc8(float (*acc)[4]) {
#pragma unroll
    for (int f = 0; f < 8; f++)
#pragma unroll
        for (int i = 0; i < 4; i++) acc[f][i] = 0.0f;
}

// ---- staging ----
__device__ __forceinline__ void stage128(u32 dst, const __half* src, int rows, int tid, int nt) {
    for (int i = tid; i < rows * 16; i += nt) {
        int r = i >> 4, c = i & 15;
        cpa16(dst + (u32)r * 256u + (u32)((c ^ (r & 7)) << 4), src + (size_t)r * 128 + c * 8);
    }
}
__device__ __forceinline__ void stageBh(u32 dst, const __half* src, int rows, int tid, int nt) {
    for (int i = tid; i < rows * 8; i += nt) {
        int r = i >> 3, c = i & 7;
        cpa16(dst + (u32)r * 128u + (u32)((c ^ (r & 7)) << 4), src + (size_t)r * 128 + c * 8);
    }
}
__device__ __forceinline__ void stage32s(u32 dst, const __half* src, int rows, int tid, int nt) {
    for (int i = tid; i < rows * 4; i += nt) {
        int r = i >> 2, c = i & 3;
        cpa16(dst + (u32)r * 64u + (u32)((c ^ (r & 3)) << 4), src + (size_t)r * 32 + c * 8);
    }
}

// ===================== prep =====================
__global__ void k_prep(const float* __restrict__ anc_wi, const float* __restrict__ anc_wh,
                       const float* __restrict__ frat_wi, const float* __restrict__ frat_wh,
                       const float* __restrict__ uf_w, const float* __restrict__ ua_w,
                       const float* __restrict__ h2o_w)
{
    int t = blockIdx.x * blockDim.x + threadIdx.x, NT = gridDim.x * blockDim.x;
    for (int i = t; i < 3 * 16384; i += NT) {
        int g = i >> 14, rem = i & 16383, k = rem >> 7, n = rem & 127;
        int d = g * 32768 + n * 128 + k;
        __half h, l;
        wsplit(anc_wh[i], h, l);  g_wt[W_ANC_WH + d] = h;  g_wt[W_ANC_WH + d + 16384] = l;
        wsplit(frat_wh[i], h, l); g_wt[W_FRAT_WH + d] = h; g_wt[W_FRAT_WH + d + 16384] = l;
    }
    for (int i = t; i < 3 * 4096; i += NT) {
        int g = i >> 12, rem = i & 4095, k = rem >> 7, n = rem & 127;
        int d = g * 8192 + n * 32 + k;
        __half h, l;
        wsplit(anc_wi[i], h, l);  g_wt[W_ANC_WI + d] = h;  g_wt[W_ANC_WI + d + 4096] = l;
        wsplit(frat_wi[i], h, l); g_wt[W_FRAT_WI + d] = h; g_wt[W_FRAT_WI + d + 4096] = l;
    }
    for (int i = t; i < 16384; i += NT) {
        int k = i >> 7, n = i & 127, d = n * 128 + k;
        __half h, l;
        wsplit(uf_w[i], h, l); g_wt[W_UF + d] = h; g_wt[W_UF + d + 16384] = l;
        wsplit(ua_w[i], h, l); g_wt[W_UA + d] = h; g_wt[W_UA + d + 16384] = l;
    }
    for (int i = t; i < 4096; i += NT) {
        int k = i >> 5, n = i & 31, d = n * 128 + k;
        __half h, l;
        wsplit(h2o_w[i], h, l); g_wt[W_H2O + d] = h; g_wt[W_H2O + d + 4096] = l;
    }
}

// ===================== init =====================
__global__ __launch_bounds__(128, 4)
void init_k(const float* __restrict__ z, const float* __restrict__ w,
            const float* __restrict__ b, __half* __restrict__ oh, __half* __restrict__ ol)
{
    const int g = threadIdx.x;
    const int row0 = blockIdx.x * 16;
    __shared__ float s[16][HD];
    for (int r = 0; r < 16; r++) s[r][g] = z[(size_t)(row0 + r) * HD + g];
    __syncthreads();
    float a[16];
#pragma unroll
    for (int r = 0; r < 16; r++) a[r] = 0.0f;
    for (int j = 0; j < HD; j++) {
        float wv = __ldg(w + (size_t)j * HD + g);
#pragma unroll
        for (int r = 0; r < 16; r++) a[r] += s[r][j] * wv;
    }
    float bg = __ldg(b + g);
#pragma unroll
    for (int r = 0; r < 16; r++) {
        __half h, l; wsplit(a[r] + bg, h, l);
        size_t o = (size_t)(row0 + r) * HD + g;
        oh[o] = h; ol[o] = l;
    }
}

// ===================== fused-kernel SMEM layout (64-row tiles) =====================
#define oAH  0
#define oAL  16384
#define oAXH 32768
#define oAXL 36864
#define oBR  40960
#define oBZ  73728
#define oBIA 106496
#define FUSE_DS 108544

__device__ __forceinline__ void load_bias(char* dsm, const float* bi, const float* bhp, int tid) {
    if (tid < 128) {
        float4 bv = make_float4(__ldg(bi + tid) + __ldg(bhp + tid),
                                __ldg(bi + 128 + tid) + __ldg(bhp + 128 + tid),
                                __ldg(bhp + 256 + tid), __ldg(bi + 256 + tid));
        *(float4*)(dsm + oBIA + tid * 16) = bv;
    }
}

// ---- full GRU body: dual r/z pass + n pass; r/z in registers ----
__device__ __forceinline__ void gru_body(char* dsm, u32 S, const __half* whT, const __half* wiT,
                                         int tid, int lane, int m0, int n0, float (*acc)[4])
{
    const int lr = lane >> 2, lc = 2 * (lane & 3);
    const float Q = 1.0f / 65535.0f;
    u32 rq[16], zq[16];

    cpwait0(); __syncthreads();

    // ---- gates r & z fused: h-part ----
    {
        float accZ[8][4];
        zacc8(acc); zacc8(accZ);
        for (int kc = 0; kc < 4; kc++)
            kdual128(acc, accZ, S + oAH, S + oAL,
                     S + oBR, S + oBR + 16384, S + oBZ, S + oBZ + 16384,
                     m0, n0, lane, kc, kc);
        __syncthreads();
        stageBh(S + oBR,         whT + 64,                 128, tid, 256);
        stageBh(S + oBR + 16384, whT + 16384 + 64,         128, tid, 256);
        stageBh(S + oBZ,         whT + 32768 + 64,         128, tid, 256);
        stageBh(S + oBZ + 16384, whT + 49152 + 64,         128, tid, 256);
        cpcommit(); cpwait0(); __syncthreads();
        for (int kc = 4; kc < 8; kc++)
            kdual128(acc, accZ, S + oAH, S + oAL,
                     S + oBR, S + oBR + 16384, S + oBZ, S + oBZ + 16384,
                     m0, n0, lane, kc, kc - 4);
        __syncthreads();
        // stage wi_r -> BR, wi_z -> BZ
        stage32s(S + oBR,        wiT,         128, tid, 256);
        stage32s(S + oBR + 8192, wiT + 4096,  128, tid, 256);
        stage32s(S + oBZ,        wiT + 8192,  128, tid, 256);
        stage32s(S + oBZ + 8192, wiT + 12288, 128, tid, 256);
        cpcommit(); cpwait0(); __syncthreads();
        for (int kc = 0; kc < 2; kc++)
            kdual32(acc, accZ, S + oAXH, S + oAXL,
                    S + oBR, S + oBR + 8192, S + oBZ, S + oBZ + 8192,
                    m0, n0, lane, kc);
        // quantize both gates
#pragma unroll
        for (int f = 0; f < 8; f++) {
            int colb = n0 + (f & 3) * 8 + lc;
            const float* bp = (const float*)(dsm + oBIA + colb * 16);
            const float* bq = (const float*)(dsm + oBIA + (colb + 1) * 16);
            rq[2 * f]     = (u32)(fsig(acc[f][0] + bp[0]) * 65535.f + 0.5f)
                          | ((u32)(fsig(acc[f][1] + bq[0]) * 65535.f + 0.5f) << 16);
            rq[2 * f + 1] = (u32)(fsig(acc[f][2] + bp[0]) * 65535.f + 0.5f)
                          | ((u32)(fsig(acc[f][3] + bq[0]) * 65535.f + 0.5f) << 16);
            zq[2 * f]     = (u32)(fsig(accZ[f][0] + bp[1]) * 65535.f + 0.5f)
                          | ((u32)(fsig(accZ[f][1] + bq[1]) * 65535.f + 0.5f) << 16);
            zq[2 * f + 1] = (u32)(fsig(accZ[f][2] + bp[1]) * 65535.f + 0.5f)
                          | ((u32)(fsig(accZ[f][3] + bq[1]) * 65535.f + 0.5f) << 16);
        }
    }
    __syncthreads();

    // ---- gate n: wh_n h0 -> BR, wi_n -> BZ ----
    stageBh(S + oBR,         whT + 65536,         128, tid, 256);
    stageBh(S + oBR + 16384, whT + 65536 + 16384, 128, tid, 256);
    stage32s(S + oBZ,        wiT + 16384,         128, tid, 256);
    stage32s(S + oBZ + 8192, wiT + 20480,         128, tid, 256);
    cpcommit(); cpwait0(); __syncthreads();

    zacc8(acc);
    for (int kc = 0; kc < 4; kc++)
        kstep128h(acc, S + oAH, S + oAL, S + oBR, S + oBR + 16384, m0, n0, lane, kc, kc);
    __syncthreads();
    stageBh(S + oBR,         whT + 65536 + 64,         128, tid, 256);
    stageBh(S + oBR + 16384, whT + 65536 + 16384 + 64, 128, tid, 256);
    cpcommit(); cpwait0(); __syncthreads();
    for (int kc = 4; kc < 8; kc++)
        kstep128h(acc, S + oAH, S + oAL, S + oBR, S + oBR + 16384, m0, n0, lane, kc, kc - 4);
    // fold r into gh2
#pragma unroll
    for (int f = 0; f < 8; f++) {
        int colb = n0 + (f & 3) * 8 + lc;
        const float* bp = (const float*)(dsm + oBIA + colb * 16);
        const float* bq = (const float*)(dsm + oBIA + (colb + 1) * 16);
#pragma unroll
        for (int hp = 0; hp < 2; hp++) {
            u32 rv = rq[2 * f + hp];
            acc[f][hp * 2]     = (float)(rv & 0xffffu) * Q * (acc[f][hp * 2]     + bp[2]) + bp[3];
            acc[f][hp * 2 + 1] = (float)(rv >> 16)     * Q * (acc[f][hp * 2 + 1] + bq[2]) + bq[3];
        }
    }
    for (int kc = 0; kc < 2; kc++)
        kstep32w(acc, S + oAXH, S + oAXL, S + oBZ, S + oBZ + 8192, m0, n0, lane, kc);

    // ---- blend ----
#pragma unroll
    for (int f = 0; f < 8; f++) {
        int colb = n0 + (f & 3) * 8 + lc;
#pragma unroll
        for (int hp = 0; hp < 2; hp++) {
            int row = m0 + (f >> 2) * 16 + lr + hp * 8;
            u32 zv = zq[2 * f + hp];
            float zz0 = (float)(zv & 0xffffu) * Q, zz1 = (float)(zv >> 16) * Q;
            float nn0 = ftanh(acc[f][hp * 2]), nn1 = ftanh(acc[f][hp * 2 + 1]);
            u32 aoff = (u32)row * 256u + (u32)((((colb >> 3) ^ (row & 7)) << 4)) + (colb & 7) * 2;
            __half2 hhv = *(__half2*)(dsm + oAH + aoff);
            __half2 hlv = *(__half2*)(dsm + oAL + aoff);
            float h0 = __half2float(__low2half(hhv)) + __half2float(__low2half(hlv));
            float h1 = __half2float(__high2half(hhv)) + __half2float(__high2half(hlv));
            acc[f][hp * 2]     = (1.0f - zz0) * nn0 + zz0 * h0;
            acc[f][hp * 2 + 1] = (1.0f - zz1) * nn1 + zz1 * h1;
        }
    }
}

// ===================== nodegru: node(pred+softmax) + anc GRU =====================
__global__ __launch_bounds__(256, 2)
void nodegru_k(const __half* __restrict__ hh, const __half* __restrict__ hl,
               const __half* __restrict__ h2oT, const float* __restrict__ h2ob,
               float* __restrict__ pred, __half* __restrict__ prh, __half* __restrict__ prl,
               const __half* __restrict__ whT, const __half* __restrict__ wiT,
               const float* __restrict__ bi, const float* __restrict__ bhp,
               __half* __restrict__ oh, __half* __restrict__ ol)
{
    extern __shared__ char dsm[];
    const u32 S = smaddr(dsm);
    const int tid = threadIdx.x, lane = tid & 31, wid = tid >> 5;
    const int row0 = blockIdx.x * 64;
    const int m0 = (wid & 1) * 32, n0 = (wid >> 1) * 32;

    load_bias(dsm, bi, bhp, tid);
    stage128(S + oAH, hh + (size_t)row0 * 128, 64, tid, 256);
    stage128(S + oAL, hl + (size_t)row0 * 128, 64, tid, 256);
    stageBh(S + oBR,         h2oT,             32, tid, 256);
    stageBh(S + oBR + 4096,  h2oT + 64,        32, tid, 256);
    stageBh(S + oBR + 16384, h2oT + 4096,      32, tid, 256);
    stageBh(S + oBR + 20480, h2oT + 4096 + 64, 32, tid, 256);
    cpcommit(); cpwait0(); __syncthreads();

    // ---- pred GEMM: 8 warps = 4 row groups x 2 col halves ----
    {
        const int pm0 = (wid & 3) * 16, Gp = wid >> 2;
        float a4[2][4];
#pragma unroll
        for (int f = 0; f < 2; f++)
#pragma unroll
            for (int i = 0; i < 4; i++) a4[f][i] = 0.0f;
        for (int kc = 0; kc < 8; kc++) {
            int half = kc >> 2, kb = kc & 3;
            u32 ahr[4], alr[4], bh[4], bl[4];
            ldmA128(ahr, S + oAH, pm0, lane, kc);
            ldmA128(alr, S + oAL, pm0, lane, kc);
            ldmBh(bh, S + oBR + half * 4096, Gp * 16, lane, kb);
            ldmBh(bl, S + oBR + 16384 + half * 4096, Gp * 16, lane, kb);
            mmaf(a4[0], ahr, bh);  mmaf(a4[1], ahr, bh + 2);
            mmaf(a4[0], ahr, bl);  mmaf(a4[1], ahr, bl + 2);
            mmaf(a4[0], alr, bh);  mmaf(a4[1], alr, bh + 2);
        }
        const int lr = lane >> 2, lc = 2 * (lane & 3);
#pragma unroll
        for (int f = 0; f < 2; f++)
#pragma unroll
            for (int i = 0; i < 4; i++) {
                int row = pm0 + lr + (i >> 1) * 8;
                int col = Gp * 16 + f * 8 + lc + (i & 1);
                *(float*)(dsm + oAXH + (row * 32 + col) * 4) = a4[f][i] + __ldg(h2ob + col);
            }
    }
    __syncthreads();

    // stage gate-r/z wh h0 -> BR/BZ (overlaps with softmax below)
    stageBh(S + oBR,         whT,                 128, tid, 256);
    stageBh(S + oBR + 16384, whT + 16384,         128, tid, 256);
    stageBh(S + oBZ,         whT + 32768,         128, tid, 256);
    stageBh(S + oBZ + 16384, whT + 32768 + 16384, 128, tid, 256);
    cpcommit();

    // softmax: read scratch into regs, sync, then write probs (over scratch)
    float v[32];
    const bool act = (tid < 64);
    if (act) {
        const float* pr = (const float*)(dsm + oAXH + tid * 128);
#pragma unroll
        for (int i = 0; i < 32; i++) v[i] = pr[i];
    }
    __syncthreads();
    if (act) {
        const int row = tid;
        float mx = -1e30f;
#pragma unroll
        for (int i = 0; i < 32; i++) mx = fmaxf(mx, v[i]);
        float e[32], sum = 0.0f;
#pragma unroll
        for (int i = 0; i < 32; i++) { e[i] = __expf(v[i] - mx); sum += e[i]; }
        float inv = __fdividef(1.0f, sum);
        size_t go = (size_t)(row0 + row) * 32;
        float4* pg = (float4*)(pred + go);
#pragma unroll
        for (int q = 0; q < 8; q++)
            pg[q] = make_float4(v[4 * q], v[4 * q + 1], v[4 * q + 2], v[4 * q + 3]);
#pragma unroll
        for (int j = 0; j < 16; j++) {
            float p0 = e[2 * j] * inv, p1 = e[2 * j + 1] * inv;
            __half H0, L0, H1, L1;
            wsplit(p0, H0, L0); wsplit(p1, H1, L1);
            __half2 hh2 = __halves2half2(H0, H1), ll2 = __halves2half2(L0, L1);
            *(__half2*)(prh + go + 2 * j) = hh2;
            *(__half2*)(prl + go + 2 * j) = ll2;
            int k = 2 * j;
            u32 xa = (u32)row * 64u + (u32)((((k >> 3) ^ (row & 3)) << 4)) + (k & 7) * 2;
            *(__half2*)(dsm + oAXH + xa) = hh2;
            *(__half2*)(dsm + oAXL + xa) = ll2;
        }
    }
    __syncthreads();

    float acc[8][4];
    gru_body(dsm, S, whT, wiT, tid, lane, m0, n0, acc);

    // store hidden
    const int lr = lane >> 2, lc = 2 * (lane & 3);
#pragma unroll
    for (int f = 0; f < 8; f++) {
        int colb = n0 + (f & 3) * 8 + lc;
#pragma unroll
        for (int hp = 0; hp < 2; hp++) {
            int row = m0 + (f >> 2) * 16 + lr + hp * 8;
            __half H0, L0, H1, L1;
            wsplit(acc[f][hp * 2], H0, L0); wsplit(acc[f][hp * 2 + 1], H1, L1);
            size_t go = (size_t)(row0 + row) * 128 + colb;
            *(__half2*)(oh + go) = __halves2half2(H0, H1);
            *(__half2*)(ol + go) = __halves2half2(L0, L1);
        }
    }
}

// ===================== grucomb: frat GRU + comb (hF stays on-chip) =====================
__global__ __launch_bounds__(256, 2)
void grucomb_k(const __half* __restrict__ xh, const __half* __restrict__ xl,
               const __half* __restrict__ hh, const __half* __restrict__ hl,
               const __half* __restrict__ whT, const __half* __restrict__ wiT,
               const float* __restrict__ bi, const float* __restrict__ bhp,
               const __half* __restrict__ pah, const __half* __restrict__ pal,
               const __half* __restrict__ ufT, const __half* __restrict__ uaT,
               const float* __restrict__ ufb, const float* __restrict__ uab,
               __half* __restrict__ oh, __half* __restrict__ ol)
{
    extern __shared__ char dsm[];
    const u32 S = smaddr(dsm);
    const int tid = threadIdx.x, lane = tid & 31, wid = tid >> 5;
    const int row0 = blockIdx.x * 64;
    const int m0 = (wid & 1) * 32, n0 = (wid >> 1) * 32;

    load_bias(dsm, bi, bhp, tid);
    stage128(S + oAH, hh + (size_t)row0 * 128, 64, tid, 256);
    stage128(S + oAL, hl + (size_t)row0 * 128, 64, tid, 256);
    stage32s(S + oAXH, xh + (size_t)row0 * 32, 64, tid, 256);
    stage32s(S + oAXL, xl + (size_t)row0 * 32, 64, tid, 256);
    stageBh(S + oBR,         whT,                 128, tid, 256);
    stageBh(S + oBR + 16384, whT + 16384,         128, tid, 256);
    stageBh(S + oBZ,         whT + 32768,         128, tid, 256);
    stageBh(S + oBZ + 16384, whT + 32768 + 16384, 128, tid, 256);
    cpcommit();

    float acc[8][4];
    gru_body(dsm, S, whT, wiT, tid, lane, m0, n0, acc);   // acc = hF

    __syncthreads();

    // prefetch uf: h0 -> BR (hi,lo), h1 -> BZ (hi,lo)
    stageBh(S + oBR,         ufT,                 128, tid, 256);
    stageBh(S + oBR + 16384, ufT + 16384,         128, tid, 256);
    stageBh(S + oBZ,         ufT + 64,            128, tid, 256);
    stageBh(S + oBZ + 16384, ufT + 16384 + 64,    128, tid, 256);
    cpcommit();

    // hF -> A panels (overwrites old h) — overlaps the uf stage
    const int lr = lane >> 2, lc = 2 * (lane & 3);
#pragma unroll
    for (int f = 0; f < 8; f++) {
        int colb = n0 + (f & 3) * 8 + lc;
#pragma unroll
        for (int hp = 0; hp < 2; hp++) {
            int row = m0 + (f >> 2) * 16 + lr + hp * 8;
            __half H0, L0, H1, L1;
            wsplit(acc[f][hp * 2], H0, L0); wsplit(acc[f][hp * 2 + 1], H1, L1);
            u32 aoff = (u32)row * 256u + (u32)((((colb >> 3) ^ (row & 7)) << 4)) + (colb & 7) * 2;
            *(__half2*)(dsm + oAH + aoff) = __halves2half2(H0, H1);
            *(__half2*)(dsm + oAL + aoff) = __halves2half2(L0, L1);
        }
    }
    cpwait0(); __syncthreads();

    // comb phase 1a: hF @ uf half0 (BR)
    zacc8(acc);
    for (int kc = 0; kc < 4; kc++)
        kstep128h(acc, S + oAH, S + oAL, S + oBR, S + oBR + 16384, m0, n0, lane, kc, kc);
    __syncthreads();          // release BR
    stageBh(S + oBR,         uaT,         128, tid, 256);   // ua h0 -> BR
    stageBh(S + oBR + 16384, uaT + 16384, 128, tid, 256);
    cpcommit();
    // comb phase 1b: hF @ uf half1 (BZ) — overlaps ua h0 stage
    for (int kc = 4; kc < 8; kc++)
        kstep128h(acc, S + oAH, S + oAL, S + oBZ, S + oBZ + 16384, m0, n0, lane, kc, kc - 4);
    __syncthreads();          // release A (hF) and BZ
    stage128(S + oAH, pah + (size_t)row0 * 128, 64, tid, 256);
    stage128(S + oAL, pal + (size_t)row0 * 128, 64, tid, 256);
    stageBh(S + oBZ,         uaT + 64,         128, tid, 256);   // ua h1 -> BZ
    stageBh(S + oBZ + 16384, uaT + 16384 + 64, 128, tid, 256);
    cpcommit(); cpwait0(); __syncthreads();

    // comb phase 2a: parent @ ua half0 (BR); 2b: half1 (BZ)
    for (int kc = 0; kc < 4; kc++)
        kstep128h(acc, S + oAH, S + oAL, S + oBR, S + oBR + 16384, m0, n0, lane, kc, kc);
    for (int kc = 4; kc < 8; kc++)
        kstep128h(acc, S + oAH, S + oAL, S + oBZ, S + oBZ + 16384, m0, n0, lane, kc, kc - 4);

    // epilogue
#pragma unroll
    for (int f = 0; f < 8; f++) {
        int colb = n0 + (f & 3) * 8 + lc;
        float b0 = __ldg(ufb + colb) + __ldg(uab + colb);
        float b1 = __ldg(ufb + colb + 1) + __ldg(uab + colb + 1);
#pragma unroll
        for (int hp = 0; hp < 2; hp++) {
            int row = m0 + (f >> 2) * 16 + lr + hp * 8;
            float o0 = ftanh(acc[f][hp * 2] + b0);
            float o1 = ftanh(acc[f][hp * 2 + 1] + b1);
            __half H0, L0, H1, L1;
            wsplit(o0, H0, L0); wsplit(o1, H1, L1);
            size_t go = (size_t)(row0 + row) * 128 + colb;
            *(__half2*)(oh + go) = __halves2half2(H0, H1);
            *(__half2*)(ol + go) = __halves2half2(L0, L1);
        }
    }
}

// ===================== leaf node (unchanged) =====================
#define nAH 0
#define nAL 16384
#define nBH 32768
#define nBL 40960
#define nPR 49152
#define NODE_DS 57344

__global__ __launch_bounds__(256, 2)
void node_k(const __half* __restrict__ hh, const __half* __restrict__ hl,
            const __half* __restrict__ h2oT, const float* __restrict__ b,
            float* __restrict__ pred, __half* __restrict__ ph, __half* __restrict__ pl)
{
    extern __shared__ char dsm[];
    const u32 S = smaddr(dsm);
    const int tid = threadIdx.x, lane = tid & 31, wid = tid >> 5;
    const int row0 = blockIdx.x * 64;

    stage128(S + nAH, hh + (size_t)row0 * 128, 64, tid, 256);
    stage128(S + nAL, hl + (size_t)row0 * 128, 64, tid, 256);
    stageBh(S + nBH, h2oT, 32, tid, 256);
    stageBh(S + nBH + 4096, h2oT + 64, 32, tid, 256);
    stageBh(S + nBL, h2oT + 4096, 32, tid, 256);
    stageBh(S + nBL + 4096, h2oT + 4096 + 64, 32, tid, 256);
    cpcommit(); cpwait0(); __syncthreads();

    {
        const int pm0 = (wid & 3) * 16, Gp = wid >> 2;
        float a4[2][4];
#pragma unroll
        for (int f = 0; f < 2; f++)
#pragma unroll
            for (int i = 0; i < 4; i++) a4[f][i] = 0.0f;
        for (int kc = 0; kc < 8; kc++) {
            int half = kc >> 2, kb = kc & 3;
            u32 ahr[4], alr[4], bh[4], bl[4];
            ldmA128(ahr, S + nAH, pm0, lane, kc);
            ldmA128(alr, S + nAL, pm0, lane, kc);
            ldmBh(bh, S + nBH + half * 4096, Gp * 16, lane, kb);
            ldmBh(bl, S + nBL + half * 4096, Gp * 16, lane, kb);
            mmaf(a4[0], ahr, bh);  mmaf(a4[1], ahr, bh + 2);
            mmaf(a4[0], ahr, bl);  mmaf(a4[1], ahr, bl + 2);
            mmaf(a4[0], alr, bh);  mmaf(a4[1], alr, bh + 2);
        }
        const int lr = lane >> 2, lc = 2 * (lane & 3);
#pragma unroll
        for (int f = 0; f < 2; f++)
#pragma unroll
            for (int i = 0; i < 4; i++) {
                int row = pm0 + lr + (i >> 1) * 8;
                int col = Gp * 16 + f * 8 + lc + (i & 1);
                *(float*)(dsm + nPR + (row * 32 + col) * 4) = a4[f][i] + __ldg(b + col);
            }
    }
    __syncthreads();
    if (tid < 64) {
        int row = tid;
        const float* pr = (const float*)(dsm + nPR + row * 128);
        float v[32], mx = -1e30f;
#pragma unroll
        for (int i = 0; i < 32; i++) { v[i] = pr[i]; mx = fmaxf(mx, v[i]); }
        float e[32], sum = 0.0f;
#pragma unroll
        for (int i = 0; i < 32; i++) { e[i] = __expf(v[i] - mx); sum += e[i]; }
        float inv = __fdividef(1.0f, sum);
        size_t go = (size_t)(row0 + row) * 32;
        float4* pg = (float4*)(pred + go);
#pragma unroll
        for (int q = 0; q < 8; q++)
            pg[q] = make_float4(v[4 * q], v[4 * q + 1], v[4 * q + 2], v[4 * q + 3]);
#pragma unroll
        for (int j = 0; j < 16; j++) {
            float p0 = e[2 * j] * inv, p1 = e[2 * j + 1] * inv;
            __half H0, L0, H1, L1;
            wsplit(p0, H0, L0); wsplit(p1, H1, L1);
            *(__half2*)(ph + go + 2 * j) = __halves2half2(H0, H1);
            *(__half2*)(pl + go + 2 * j) = __halves2half2(L0, L1);
        }
    }
}

// ===================== host =====================
namespace {
struct LCtx {
    const __half* wt;
    const float *h2o_b;
    const float *anc_bi, *anc_bh, *frat_bi, *frat_bh;
    const float *ua_b, *uf_b;
    __half *hAh, *hAl, *prh, *prl;
    float* out;
    int idx;
};

void rec(LCtx& c, int L, int d)
{
    size_t hL = (size_t)L * BATCH * HD, hL1 = (size_t)(L + 1) * BATCH * HD;
    size_t pL = (size_t)L * BATCH * OD, pL1 = (size_t)(L + 1) * BATCH * OD;

    if (d == 0) {
        node_k<<<BATCH / 64, 256, NODE_DS>>>(c.hAh + hL, c.hAl + hL,
                                             c.wt + W_H2O, c.h2o_b,
                                             c.out + (size_t)c.idx * BATCH * OD,
                                             c.prh + pL, c.prl + pL);
        c.idx++;
        return;
    }

    nodegru_k<<<BATCH / 64, 256, FUSE_DS>>>(c.hAh + hL, c.hAl + hL,
                                            c.wt + W_H2O, c.h2o_b,
                                            c.out + (size_t)c.idx * BATCH * OD,
                                            c.prh + pL, c.prl + pL,
                                            c.wt + W_ANC_WH, c.wt + W_ANC_WI,
                                            c.anc_bi, c.anc_bh,
                                            c.hAh + hL1, c.hAl + hL1);
    c.idx++;
    rec(c, L + 1, d - 1);

    grucomb_k<<<BATCH / 64, 256, FUSE_DS>>>(c.prh + pL1, c.prl + pL1,
                                            c.hAh + hL1, c.hAl + hL1,
                                            c.wt + W_FRAT_WH, c.wt + W_FRAT_WI,
                                            c.frat_bi, c.frat_bh,
                                            c.hAh + hL, c.hAl + hL,
                                            c.wt + W_UF, c.wt + W_UA,
                                            c.uf_b, c.ua_b,
                                            c.hAh + hL1, c.hAl + hL1);
    rec(c, L + 1, d - 1);
}
} // namespace

extern "C" void kernel_launch(void* const* d_in, const int* in_sizes, int n_in,
                              void* d_out, int out_size)
{
    const float* z       = (const float*)d_in[0];
    const float* z2h_w   = (const float*)d_in[1];
    const float* z2h_b   = (const float*)d_in[2];
    const float* h2o_w   = (const float*)d_in[3];
    const float* h2o_b   = (const float*)d_in[4];
    const float* anc_wi  = (const float*)d_in[5];
    const float* anc_wh  = (const float*)d_in[6];
    const float* anc_bi  = (const float*)d_in[7];
    const float* anc_bh  = (const float*)d_in[8];
    const float* frat_wi = (const float*)d_in[9];
    const float* frat_wh = (const float*)d_in[10];
    const float* frat_bi = (const float*)d_in[11];
    const float* frat_bh = (const float*)d_in[12];
    const float* ua_w    = (const float*)d_in[13];
    const float* ua_b    = (const float*)d_in[14];
    const float* uf_w    = (const float*)d_in[15];
    const float* uf_b    = (const float*)d_in[16];

    cudaFuncSetAttribute(nodegru_k, cudaFuncAttributeMaxDynamicSharedMemorySize, FUSE_DS);
    cudaFuncSetAttribute(grucomb_k, cudaFuncAttributeMaxDynamicSharedMemorySize, FUSE_DS);
    cudaFuncSetAttribute(node_k,    cudaFuncAttributeMaxDynamicSharedMemorySize, NODE_DS);

    __half *wt, *hAh, *hAl, *prh, *prl;
    cudaGetSymbolAddress((void**)&wt, g_wt);
    cudaGetSymbolAddress((void**)&hAh, g_hAh);
    cudaGetSymbolAddress((void**)&hAl, g_hAl);
    cudaGetSymbolAddress((void**)&prh, g_prh);
    cudaGetSymbolAddress((void**)&prl, g_prl);

    k_prep<<<128, 256>>>(anc_wi, anc_wh, frat_wi, frat_wh, uf_w, ua_w, h2o_w);
    init_k<<<BATCH / 16, 128>>>(z, z2h_w, z2h_b, hAh, hAl);

    LCtx c;
    c.wt = wt; c.h2o_b = h2o_b;
    c.anc_bi = anc_bi; c.anc_bh = anc_bh;
    c.frat_bi = frat_bi; c.frat_bh = frat_bh;
    c.ua_b = ua_b; c.uf_b = uf_b;
    c.hAh = hAh; c.hAl = hAl;
    c.prh = prh; c.prl = prl;
    c.out = (float*)d_out;
    c.idx = 0;
    rec(c, 0, DEPTH);
}

// round 14
// speedup vs baseline: 1.0046x; 1.0046x over previous
#include <cuda_runtime.h>
#include <cuda_fp16.h>
#include <cstdint>

#define BATCH 32768
#define HD 128
#define OD 32
#define DEPTH 5
typedef uint32_t u32;

// ---- weight tile offsets in g_wt (halves) ----
#define W_ANC_WH  0
#define W_FRAT_WH 98304
#define W_ANC_WI  196608
#define W_FRAT_WI 221184
#define W_UF      245760
#define W_UA      278528
#define W_H2O     311296
__device__ __half g_wt[319488];

// hidden buffers: slot = level*2 + parity (parity 0: first-child hidden from nodegru,
// parity 1: second-child hidden from grucomb). Level 0 uses parity 0 only.
__device__ __half g_hAh[(DEPTH + 1) * 2][BATCH * HD];
__device__ __half g_hAl[(DEPTH + 1) * 2][BATCH * HD];
__device__ __half g_prh[DEPTH + 1][BATCH * OD];
__device__ __half g_prl[DEPTH + 1][BATCH * OD];

// ===================== helpers =====================
__device__ __forceinline__ u32 smaddr(const void* p) {
    u32 a;
    asm("{ .reg .u64 t; cvta.to.shared.u64 t, %1; cvt.u32.u64 %0, t; }" : "=r"(a) : "l"(p));
    return a;
}
__device__ __forceinline__ void cpa16(u32 d, const void* s) {
    asm volatile("cp.async.cg.shared.global [%0], [%1], 16;" :: "r"(d), "l"(s) : "memory");
}
__device__ __forceinline__ void cpcommit() {
    asm volatile("cp.async.commit_group;" ::: "memory");
}
__device__ __forceinline__ void cpwait0() {
    asm volatile("cp.async.wait_group 0;" ::: "memory");
}
__device__ __forceinline__ void ldm4(u32* r, u32 a) {
    asm volatile("ldmatrix.sync.aligned.m8n8.x4.shared.b16 {%0,%1,%2,%3}, [%4];"
                 : "=r"(r[0]), "=r"(r[1]), "=r"(r[2]), "=r"(r[3]) : "r"(a));
}
__device__ __forceinline__ void mmaf(float* c, const u32* a, const u32* b) {
    asm volatile(
        "mma.sync.aligned.m16n8k16.row.col.f32.f16.f16.f32 "
        "{%0,%1,%2,%3},{%4,%5,%6,%7},{%8,%9},{%0,%1,%2,%3};"
        : "+f"(c[0]), "+f"(c[1]), "+f"(c[2]), "+f"(c[3])
        : "r"(a[0]), "r"(a[1]), "r"(a[2]), "r"(a[3]), "r"(b[0]), "r"(b[1]));
}
__device__ __forceinline__ float fsig(float x)  { return __fdividef(1.0f, 1.0f + __expf(-x)); }
__device__ __forceinline__ float ftanh(float x) { float u = __expf(2.0f * x); return 1.0f - __fdividef(2.0f, u + 1.0f); }
__device__ __forceinline__ void wsplit(float v, __half& h, __half& l) {
    h = __float2half_rn(v);
    l = __float2half_rn(v - __half2float(h));
}

// ---- ldmatrix addressing ----
__device__ __forceinline__ void ldmA128(u32* r, u32 base, int m0, int lane, int kc) {
    int row = m0 + (lane & 15), c16 = 2 * kc + (lane >> 4);
    ldm4(r, base + (u32)row * 256u + (u32)((c16 ^ (row & 7)) << 4));
}
__device__ __forceinline__ void ldmBh(u32* r, u32 base, int n0, int lane, int kc) {
    int row = n0 + (lane & 7) + ((lane >> 4) << 3), c8 = 2 * kc + ((lane >> 3) & 1);
    ldm4(r, base + (u32)row * 128u + (u32)((c8 ^ (row & 7)) << 4));
}
__device__ __forceinline__ void ldmA32(u32* r, u32 base, int m0, int lane, int kc) {
    int row = m0 + (lane & 15), c4 = 2 * kc + (lane >> 4);
    ldm4(r, base + (u32)row * 64u + (u32)((c4 ^ (row & 3)) << 4));
}
__device__ __forceinline__ void ldmB32(u32* r, u32 base, int n0, int lane, int kc) {
    int row = n0 + (lane & 7) + ((lane >> 4) << 3), c4 = 2 * kc + ((lane >> 3) & 1);
    ldm4(r, base + (u32)row * 64u + (u32)((c4 ^ (row & 3)) << 4));
}

// ---- single-gate 32x32 kstep (B from half-K panel: hi at BH, lo at BL) ----
__device__ __forceinline__ void kstep128h(float (*acc)[4], u32 AH, u32 AL, u32 BH, u32 BL,
                                          int m0, int n0, int lane, int kcA, int kcB) {
    u32 a[4][4];
    ldmA128(a[0], AH, m0, lane, kcA);      ldmA128(a[1], AH, m0 + 16, lane, kcA);
    ldmA128(a[2], AL, m0, lane, kcA);      ldmA128(a[3], AL, m0 + 16, lane, kcA);
#pragma unroll
    for (int G = 0; G < 2; G++) {
        u32 bh[4], bl[4];
        ldmBh(bh, BH, n0 + G * 16, lane, kcB);
        ldmBh(bl, BL, n0 + G * 16, lane, kcB);
#pragma unroll
        for (int mf = 0; mf < 2; mf++) {
            float* c0 = acc[mf * 4 + G * 2];
            float* c1 = acc[mf * 4 + G * 2 + 1];
            mmaf(c0, a[mf], bh);     mmaf(c1, a[mf], bh + 2);
            mmaf(c0, a[mf], bl);     mmaf(c1, a[mf], bl + 2);
            mmaf(c0, a[2 + mf], bh); mmaf(c1, a[2 + mf], bh + 2);
        }
    }
}
__device__ __forceinline__ void kstep32w(float (*acc)[4], u32 AH, u32 AL, u32 BH, u32 BL,
                                         int m0, int n0, int lane, int kc) {
    u32 a[4][4];
    ldmA32(a[0], AH, m0, lane, kc);      ldmA32(a[1], AH, m0 + 16, lane, kc);
    ldmA32(a[2], AL, m0, lane, kc);      ldmA32(a[3], AL, m0 + 16, lane, kc);
#pragma unroll
    for (int G = 0; G < 2; G++) {
        u32 bh[4], bl[4];
        ldmB32(bh, BH, n0 + G * 16, lane, kc);
        ldmB32(bl, BL, n0 + G * 16, lane, kc);
#pragma unroll
        for (int mf = 0; mf < 2; mf++) {
            float* c0 = acc[mf * 4 + G * 2];
            float* c1 = acc[mf * 4 + G * 2 + 1];
            mmaf(c0, a[mf], bh);     mmaf(c1, a[mf], bh + 2);
            mmaf(c0, a[mf], bl);     mmaf(c1, a[mf], bl + 2);
            mmaf(c0, a[2 + mf], bh); mmaf(c1, a[2 + mf], bh + 2);
        }
    }
}
// ---- dual-gate ksteps: A loaded once, feeds both gate-r and gate-z accumulators ----
__device__ __forceinline__ void kdual128(float (*aR)[4], float (*aZ)[4], u32 AH, u32 AL,
                                         u32 BRh, u32 BRl, u32 BZh, u32 BZl,
                                         int m0, int n0, int lane, int kcA, int kcB) {
    u32 a[4][4];
    ldmA128(a[0], AH, m0, lane, kcA);      ldmA128(a[1], AH, m0 + 16, lane, kcA);
    ldmA128(a[2], AL, m0, lane, kcA);      ldmA128(a[3], AL, m0 + 16, lane, kcA);
    {
        u32 bh[4], bl[4];
        ldmBh(bh, BRh, n0, lane, kcB);  ldmBh(bl, BRl, n0, lane, kcB);
#pragma unroll
        for (int mf = 0; mf < 2; mf++) {
            float* c0 = aR[mf * 4]; float* c1 = aR[mf * 4 + 1];
            mmaf(c0, a[mf], bh);     mmaf(c1, a[mf], bh + 2);
            mmaf(c0, a[mf], bl);     mmaf(c1, a[mf], bl + 2);
            mmaf(c0, a[2 + mf], bh); mmaf(c1, a[2 + mf], bh + 2);
        }
        ldmBh(bh, BRh, n0 + 16, lane, kcB);  ldmBh(bl, BRl, n0 + 16, lane, kcB);
#pragma unroll
        for (int mf = 0; mf < 2; mf++) {
            float* c0 = aR[mf * 4 + 2]; float* c1 = aR[mf * 4 + 3];
            mmaf(c0, a[mf], bh);     mmaf(c1, a[mf], bh + 2);
            mmaf(c0, a[mf], bl);     mmaf(c1, a[mf], bl + 2);
            mmaf(c0, a[2 + mf], bh); mmaf(c1, a[2 + mf], bh + 2);
        }
    }
    {
        u32 bh[4], bl[4];
        ldmBh(bh, BZh, n0, lane, kcB);  ldmBh(bl, BZl, n0, lane, kcB);
#pragma unroll
        for (int mf = 0; mf < 2; mf++) {
            float* c0 = aZ[mf * 4]; float* c1 = aZ[mf * 4 + 1];
            mmaf(c0, a[mf], bh);     mmaf(c1, a[mf], bh + 2);
            mmaf(c0, a[mf], bl);     mmaf(c1, a[mf], bl + 2);
            mmaf(c0, a[2 + mf], bh); mmaf(c1, a[2 + mf], bh + 2);
        }
        ldmBh(bh, BZh, n0 + 16, lane, kcB);  ldmBh(bl, BZl, n0 + 16, lane, kcB);
#pragma unroll
        for (int mf = 0; mf < 2; mf++) {
            float* c0 = aZ[mf * 4 + 2]; float* c1 = aZ[mf * 4 + 3];
            mmaf(c0, a[mf], bh);     mmaf(c1, a[mf], bh + 2);
            mmaf(c0, a[mf], bl);     mmaf(c1, a[mf], bl + 2);
            mmaf(c0, a[2 + mf], bh); mmaf(c1, a[2 + mf], bh + 2);
        }
    }
}
__device__ __forceinline__ void kdual32(float (*aR)[4], float (*aZ)[4], u32 AH, u32 AL,
                                        u32 BRh, u32 BRl, u32 BZh, u32 BZl,
                                        int m0, int n0, int lane, int kc) {
    u32 a[4][4];
    ldmA32(a[0], AH, m0, lane, kc);      ldmA32(a[1], AH, m0 + 16, lane, kc);
    ldmA32(a[2], AL, m0, lane, kc);      ldmA32(a[3], AL, m0 + 16, lane, kc);
#pragma unroll
    for (int G = 0; G < 2; G++) {
        {
            u32 bh[4], bl[4];
            ldmB32(bh, BRh, n0 + G * 16, lane, kc);
            ldmB32(bl, BRl, n0 + G * 16, lane, kc);
#pragma unroll
            for (int mf = 0; mf < 2; mf++) {
                float* c0 = aR[mf * 4 + G * 2];
                float* c1 = aR[mf * 4 + G * 2 + 1];
                mmaf(c0, a[mf], bh);     mmaf(c1, a[mf], bh + 2);
                mmaf(c0, a[mf], bl);     mmaf(c1, a[mf], bl + 2);
                mmaf(c0, a[2 + mf], bh); mmaf(c1, a[2 + mf], bh + 2);
            }
        }
        {
            u32 bh[4], bl[4];
            ldmB32(bh, BZh, n0 + G * 16, lane, kc);
            ldmB32(bl, BZl, n0 + G * 16, lane, kc);
#pragma unroll
            for (int mf = 0; mf < 2; mf++) {
                float* c0 = aZ[mf * 4 + G * 2];
                float* c1 = aZ[mf * 4 + G * 2 + 1];
                mmaf(c0, a[mf], bh);     mmaf(c1, a[mf], bh + 2);
                mmaf(c0, a[mf], bl);     mmaf(c1, a[mf], bl + 2);
                mmaf(c0, a[2 + mf], bh); mmaf(c1, a[2 + mf], bh + 2);
            }
        }
    }
}
__device__ __forceinline__ void zacc8(float (*acc)[4]) {
#pragma unroll
    for (int f = 0; f < 8; f++)
#pragma unroll
        for (int i = 0; i < 4; i++) acc[f][i] = 0.0f;
}

// ---- staging ----
__device__ __forceinline__ void stage128(u32 dst, const __half* src, int rows, int tid, int nt) {
    for (int i = tid; i < rows * 16; i += nt) {
        int r = i >> 4, c = i & 15;
        cpa16(dst + (u32)r * 256u + (u32)((c ^ (r & 7)) << 4), src + (size_t)r * 128 + c * 8);
    }
}
__device__ __forceinline__ void stageBh(u32 dst, const __half* src, int rows, int tid, int nt) {
    for (int i = tid; i < rows * 8; i += nt) {
        int r = i >> 3, c = i & 7;
        cpa16(dst + (u32)r * 128u + (u32)((c ^ (r & 7)) << 4), src + (size_t)r * 128 + c * 8);
    }
}
__device__ __forceinline__ void stage32s(u32 dst, const __half* src, int rows, int tid, int nt) {
    for (int i = tid; i < rows * 4; i += nt) {
        int r = i >> 2, c = i & 3;
        cpa16(dst + (u32)r * 64u + (u32)((c ^ (r & 3)) << 4), src + (size_t)r * 32 + c * 8);
    }
}

// ===================== prep =====================
__global__ void k_prep(const float* __restrict__ anc_wi, const float* __restrict__ anc_wh,
                       const float* __restrict__ frat_wi, const float* __restrict__ frat_wh,
                       const float* __restrict__ uf_w, const float* __restrict__ ua_w,
                       const float* __restrict__ h2o_w)
{
    int t = blockIdx.x * blockDim.x + threadIdx.x, NT = gridDim.x * blockDim.x;
    for (int i = t; i < 3 * 16384; i += NT) {
        int g = i >> 14, rem = i & 16383, k = rem >> 7, n = rem & 127;
        int d = g * 32768 + n * 128 + k;
        __half h, l;
        wsplit(anc_wh[i], h, l);  g_wt[W_ANC_WH + d] = h;  g_wt[W_ANC_WH + d + 16384] = l;
        wsplit(frat_wh[i], h, l); g_wt[W_FRAT_WH + d] = h; g_wt[W_FRAT_WH + d + 16384] = l;
    }
    for (int i = t; i < 3 * 4096; i += NT) {
        int g = i >> 12, rem = i & 4095, k = rem >> 7, n = rem & 127;
        int d = g * 8192 + n * 32 + k;
        __half h, l;
        wsplit(anc_wi[i], h, l);  g_wt[W_ANC_WI + d] = h;  g_wt[W_ANC_WI + d + 4096] = l;
        wsplit(frat_wi[i], h, l); g_wt[W_FRAT_WI + d] = h; g_wt[W_FRAT_WI + d + 4096] = l;
    }
    for (int i = t; i < 16384; i += NT) {
        int k = i >> 7, n = i & 127, d = n * 128 + k;
        __half h, l;
        wsplit(uf_w[i], h, l); g_wt[W_UF + d] = h; g_wt[W_UF + d + 16384] = l;
        wsplit(ua_w[i], h, l); g_wt[W_UA + d] = h; g_wt[W_UA + d + 16384] = l;
    }
    for (int i = t; i < 4096; i += NT) {
        int k = i >> 5, n = i & 31, d = n * 128 + k;
        __half h, l;
        wsplit(h2o_w[i], h, l); g_wt[W_H2O + d] = h; g_wt[W_H2O + d + 4096] = l;
    }
}

// ===================== init =====================
__global__ __launch_bounds__(128, 4)
void init_k(const float* __restrict__ z, const float* __restrict__ w,
            const float* __restrict__ b, __half* __restrict__ oh, __half* __restrict__ ol)
{
    const int g = threadIdx.x;
    const int row0 = blockIdx.x * 16;
    __shared__ float s[16][HD];
    for (int r = 0; r < 16; r++) s[r][g] = z[(size_t)(row0 + r) * HD + g];
    __syncthreads();
    float a[16];
#pragma unroll
    for (int r = 0; r < 16; r++) a[r] = 0.0f;
    for (int j = 0; j < HD; j++) {
        float wv = __ldg(w + (size_t)j * HD + g);
#pragma unroll
        for (int r = 0; r < 16; r++) a[r] += s[r][j] * wv;
    }
    float bg = __ldg(b + g);
#pragma unroll
    for (int r = 0; r < 16; r++) {
        __half h, l; wsplit(a[r] + bg, h, l);
        size_t o = (size_t)(row0 + r) * HD + g;
        oh[o] = h; ol[o] = l;
    }
}

// ===================== fused-kernel SMEM layout (64-row tiles) =====================
#define oAH  0
#define oAL  16384
#define oAXH 32768
#define oAXL 36864
#define oBR  40960
#define oBZ  73728
#define oBIA 106496
#define FUSE_DS 108544

__device__ __forceinline__ void load_bias(char* dsm, const float* bi, const float* bhp, int tid) {
    if (tid < 128) {
        float4 bv = make_float4(__ldg(bi + tid) + __ldg(bhp + tid),
                                __ldg(bi + 128 + tid) + __ldg(bhp + 128 + tid),
                                __ldg(bhp + 256 + tid), __ldg(bi + 256 + tid));
        *(float4*)(dsm + oBIA + tid * 16) = bv;
    }
}

// ---- full GRU body (R12): dual r/z pass + n pass; r/z in registers ----
__device__ __forceinline__ void gru_body(char* dsm, u32 S, const __half* whT, const __half* wiT,
                                         int tid, int lane, int m0, int n0, float (*acc)[4])
{
    const int lr = lane >> 2, lc = 2 * (lane & 3);
    const float Q = 1.0f / 65535.0f;
    u32 rq[16], zq[16];

    cpwait0(); __syncthreads();

    {
        float accZ[8][4];
        zacc8(acc); zacc8(accZ);
        for (int kc = 0; kc < 4; kc++)
            kdual128(acc, accZ, S + oAH, S + oAL,
                     S + oBR, S + oBR + 16384, S + oBZ, S + oBZ + 16384,
                     m0, n0, lane, kc, kc);
        __syncthreads();
        stageBh(S + oBR,         whT + 64,                 128, tid, 256);
        stageBh(S + oBR + 16384, whT + 16384 + 64,         128, tid, 256);
        stageBh(S + oBZ,         whT + 32768 + 64,         128, tid, 256);
        stageBh(S + oBZ + 16384, whT + 49152 + 64,         128, tid, 256);
        cpcommit(); cpwait0(); __syncthreads();
        for (int kc = 4; kc < 8; kc++)
            kdual128(acc, accZ, S + oAH, S + oAL,
                     S + oBR, S + oBR + 16384, S + oBZ, S + oBZ + 16384,
                     m0, n0, lane, kc, kc - 4);
        __syncthreads();
        stage32s(S + oBR,        wiT,         128, tid, 256);
        stage32s(S + oBR + 8192, wiT + 4096,  128, tid, 256);
        stage32s(S + oBZ,        wiT + 8192,  128, tid, 256);
        stage32s(S + oBZ + 8192, wiT + 12288, 128, tid, 256);
        cpcommit(); cpwait0(); __syncthreads();
        for (int kc = 0; kc < 2; kc++)
            kdual32(acc, accZ, S + oAXH, S + oAXL,
                    S + oBR, S + oBR + 8192, S + oBZ, S + oBZ + 8192,
                    m0, n0, lane, kc);
#pragma unroll
        for (int f = 0; f < 8; f++) {
            int colb = n0 + (f & 3) * 8 + lc;
            const float* bp = (const float*)(dsm + oBIA + colb * 16);
            const float* bq = (const float*)(dsm + oBIA + (colb + 1) * 16);
            rq[2 * f]     = (u32)(fsig(acc[f][0] + bp[0]) * 65535.f + 0.5f)
                          | ((u32)(fsig(acc[f][1] + bq[0]) * 65535.f + 0.5f) << 16);
            rq[2 * f + 1] = (u32)(fsig(acc[f][2] + bp[0]) * 65535.f + 0.5f)
                          | ((u32)(fsig(acc[f][3] + bq[0]) * 65535.f + 0.5f) << 16);
            zq[2 * f]     = (u32)(fsig(accZ[f][0] + bp[1]) * 65535.f + 0.5f)
                          | ((u32)(fsig(accZ[f][1] + bq[1]) * 65535.f + 0.5f) << 16);
            zq[2 * f + 1] = (u32)(fsig(accZ[f][2] + bp[1]) * 65535.f + 0.5f)
                          | ((u32)(fsig(accZ[f][3] + bq[1]) * 65535.f + 0.5f) << 16);
        }
    }
    __syncthreads();

    stageBh(S + oBR,         whT + 65536,         128, tid, 256);
    stageBh(S + oBR + 16384, whT + 65536 + 16384, 128, tid, 256);
    stage32s(S + oBZ,        wiT + 16384,         128, tid, 256);
    stage32s(S + oBZ + 8192, wiT + 20480,         128, tid, 256);
    cpcommit(); cpwait0(); __syncthreads();

    zacc8(acc);
    for (int kc = 0; kc < 4; kc++)
        kstep128h(acc, S + oAH, S + oAL, S + oBR, S + oBR + 16384, m0, n0, lane, kc, kc);
    __syncthreads();
    stageBh(S + oBR,         whT + 65536 + 64,         128, tid, 256);
    stageBh(S + oBR + 16384, whT + 65536 + 16384 + 64, 128, tid, 256);
    cpcommit(); cpwait0(); __syncthreads();
    for (int kc = 4; kc < 8; kc++)
        kstep128h(acc, S + oAH, S + oAL, S + oBR, S + oBR + 16384, m0, n0, lane, kc, kc - 4);
#pragma unroll
    for (int f = 0; f < 8; f++) {
        int colb = n0 + (f & 3) * 8 + lc;
        const float* bp = (const float*)(dsm + oBIA + colb * 16);
        const float* bq = (const float*)(dsm + oBIA + (colb + 1) * 16);
#pragma unroll
        for (int hp = 0; hp < 2; hp++) {
            u32 rv = rq[2 * f + hp];
            acc[f][hp * 2]     = (float)(rv & 0xffffu) * Q * (acc[f][hp * 2]     + bp[2]) + bp[3];
            acc[f][hp * 2 + 1] = (float)(rv >> 16)     * Q * (acc[f][hp * 2 + 1] + bq[2]) + bq[3];
        }
    }
    for (int kc = 0; kc < 2; kc++)
        kstep32w(acc, S + oAXH, S + oAXL, S + oBZ, S + oBZ + 8192, m0, n0, lane, kc);

#pragma unroll
    for (int f = 0; f < 8; f++) {
        int colb = n0 + (f & 3) * 8 + lc;
#pragma unroll
        for (int hp = 0; hp < 2; hp++) {
            int row = m0 + (f >> 2) * 16 + lr + hp * 8;
            u32 zv = zq[2 * f + hp];
            float zz0 = (float)(zv & 0xffffu) * Q, zz1 = (float)(zv >> 16) * Q;
            float nn0 = ftanh(acc[f][hp * 2]), nn1 = ftanh(acc[f][hp * 2 + 1]);
            u32 aoff = (u32)row * 256u + (u32)((((colb >> 3) ^ (row & 7)) << 4)) + (colb & 7) * 2;
            __half2 hhv = *(__half2*)(dsm + oAH + aoff);
            __half2 hlv = *(__half2*)(dsm + oAL + aoff);
            float h0 = __half2float(__low2half(hhv)) + __half2float(__low2half(hlv));
            float h1 = __half2float(__high2half(hhv)) + __half2float(__high2half(hlv));
            acc[f][hp * 2]     = (1.0f - zz0) * nn0 + zz0 * h0;
            acc[f][hp * 2 + 1] = (1.0f - zz1) * nn1 + zz1 * h1;
        }
    }
}

// ===================== nodegru =====================
__global__ __launch_bounds__(256, 2)
void nodegru_k(const __half* __restrict__ hh, const __half* __restrict__ hl,
               const __half* __restrict__ h2oT, const float* __restrict__ h2ob,
               float* __restrict__ pred, __half* __restrict__ prh, __half* __restrict__ prl,
               const __half* __restrict__ whT, const __half* __restrict__ wiT,
               const float* __restrict__ bi, const float* __restrict__ bhp,
               __half* __restrict__ oh, __half* __restrict__ ol)
{
    extern __shared__ char dsm[];
    const u32 S = smaddr(dsm);
    const int tid = threadIdx.x, lane = tid & 31, wid = tid >> 5;
    const int row0 = blockIdx.x * 64;
    const int m0 = (wid & 1) * 32, n0 = (wid >> 1) * 32;

    load_bias(dsm, bi, bhp, tid);
    stage128(S + oAH, hh + (size_t)row0 * 128, 64, tid, 256);
    stage128(S + oAL, hl + (size_t)row0 * 128, 64, tid, 256);
    stageBh(S + oBR,         h2oT,             32, tid, 256);
    stageBh(S + oBR + 4096,  h2oT + 64,        32, tid, 256);
    stageBh(S + oBR + 16384, h2oT + 4096,      32, tid, 256);
    stageBh(S + oBR + 20480, h2oT + 4096 + 64, 32, tid, 256);
    cpcommit(); cpwait0(); __syncthreads();

    {
        const int pm0 = (wid & 3) * 16, Gp = wid >> 2;
        float a4[2][4];
#pragma unroll
        for (int f = 0; f < 2; f++)
#pragma unroll
            for (int i = 0; i < 4; i++) a4[f][i] = 0.0f;
        for (int kc = 0; kc < 8; kc++) {
            int half = kc >> 2, kb = kc & 3;
            u32 ahr[4], alr[4], bh[4], bl[4];
            ldmA128(ahr, S + oAH, pm0, lane, kc);
            ldmA128(alr, S + oAL, pm0, lane, kc);
            ldmBh(bh, S + oBR + half * 4096, Gp * 16, lane, kb);
            ldmBh(bl, S + oBR + 16384 + half * 4096, Gp * 16, lane, kb);
            mmaf(a4[0], ahr, bh);  mmaf(a4[1], ahr, bh + 2);
            mmaf(a4[0], ahr, bl);  mmaf(a4[1], ahr, bl + 2);
            mmaf(a4[0], alr, bh);  mmaf(a4[1], alr, bh + 2);
        }
        const int lr = lane >> 2, lc = 2 * (lane & 3);
#pragma unroll
        for (int f = 0; f < 2; f++)
#pragma unroll
            for (int i = 0; i < 4; i++) {
                int row = pm0 + lr + (i >> 1) * 8;
                int col = Gp * 16 + f * 8 + lc + (i & 1);
                *(float*)(dsm + oAXH + (row * 32 + col) * 4) = a4[f][i] + __ldg(h2ob + col);
            }
    }
    __syncthreads();

    stageBh(S + oBR,         whT,                 128, tid, 256);
    stageBh(S + oBR + 16384, whT + 16384,         128, tid, 256);
    stageBh(S + oBZ,         whT + 32768,         128, tid, 256);
    stageBh(S + oBZ + 16384, whT + 32768 + 16384, 128, tid, 256);
    cpcommit();

    float v[32];
    const bool act = (tid < 64);
    if (act) {
        const float* pr = (const float*)(dsm + oAXH + tid * 128);
#pragma unroll
        for (int i = 0; i < 32; i++) v[i] = pr[i];
    }
    __syncthreads();
    if (act) {
        const int row = tid;
        float mx = -1e30f;
#pragma unroll
        for (int i = 0; i < 32; i++) mx = fmaxf(mx, v[i]);
        float e[32], sum = 0.0f;
#pragma unroll
        for (int i = 0; i < 32; i++) { e[i] = __expf(v[i] - mx); sum += e[i]; }
        float inv = __fdividef(1.0f, sum);
        size_t go = (size_t)(row0 + row) * 32;
        float4* pg = (float4*)(pred + go);
#pragma unroll
        for (int q = 0; q < 8; q++)
            pg[q] = make_float4(v[4 * q], v[4 * q + 1], v[4 * q + 2], v[4 * q + 3]);
#pragma unroll
        for (int j = 0; j < 16; j++) {
            float p0 = e[2 * j] * inv, p1 = e[2 * j + 1] * inv;
            __half H0, L0, H1, L1;
            wsplit(p0, H0, L0); wsplit(p1, H1, L1);
            __half2 hh2 = __halves2half2(H0, H1), ll2 = __halves2half2(L0, L1);
            *(__half2*)(prh + go + 2 * j) = hh2;
            *(__half2*)(prl + go + 2 * j) = ll2;
            int k = 2 * j;
            u32 xa = (u32)row * 64u + (u32)((((k >> 3) ^ (row & 3)) << 4)) + (k & 7) * 2;
            *(__half2*)(dsm + oAXH + xa) = hh2;
            *(__half2*)(dsm + oAXL + xa) = ll2;
        }
    }
    __syncthreads();

    float acc[8][4];
    gru_body(dsm, S, whT, wiT, tid, lane, m0, n0, acc);

    const int lr = lane >> 2, lc = 2 * (lane & 3);
#pragma unroll
    for (int f = 0; f < 8; f++) {
        int colb = n0 + (f & 3) * 8 + lc;
#pragma unroll
        for (int hp = 0; hp < 2; hp++) {
            int row = m0 + (f >> 2) * 16 + lr + hp * 8;
            __half H0, L0, H1, L1;
            wsplit(acc[f][hp * 2], H0, L0); wsplit(acc[f][hp * 2 + 1], H1, L1);
            size_t go = (size_t)(row0 + row) * 128 + colb;
            *(__half2*)(oh + go) = __halves2half2(H0, H1);
            *(__half2*)(ol + go) = __halves2half2(L0, L1);
        }
    }
}

// ===================== grucomb =====================
__global__ __launch_bounds__(256, 2)
void grucomb_k(const __half* __restrict__ xh, const __half* __restrict__ xl,
               const __half* __restrict__ hh, const __half* __restrict__ hl,
               const __half* __restrict__ whT, const __half* __restrict__ wiT,
               const float* __restrict__ bi, const float* __restrict__ bhp,
               const __half* __restrict__ pah, const __half* __restrict__ pal,
               const __half* __restrict__ ufT, const __half* __restrict__ uaT,
               const float* __restrict__ ufb, const float* __restrict__ uab,
               __half* __restrict__ oh, __half* __restrict__ ol)
{
    extern __shared__ char dsm[];
    const u32 S = smaddr(dsm);
    const int tid = threadIdx.x, lane = tid & 31, wid = tid >> 5;
    const int row0 = blockIdx.x * 64;
    const int m0 = (wid & 1) * 32, n0 = (wid >> 1) * 32;

    load_bias(dsm, bi, bhp, tid);
    stage128(S + oAH, hh + (size_t)row0 * 128, 64, tid, 256);
    stage128(S + oAL, hl + (size_t)row0 * 128, 64, tid, 256);
    stage32s(S + oAXH, xh + (size_t)row0 * 32, 64, tid, 256);
    stage32s(S + oAXL, xl + (size_t)row0 * 32, 64, tid, 256);
    stageBh(S + oBR,         whT,                 128, tid, 256);
    stageBh(S + oBR + 16384, whT + 16384,         128, tid, 256);
    stageBh(S + oBZ,         whT + 32768,         128, tid, 256);
    stageBh(S + oBZ + 16384, whT + 32768 + 16384, 128, tid, 256);
    cpcommit();

    float acc[8][4];
    gru_body(dsm, S, whT, wiT, tid, lane, m0, n0, acc);

    __syncthreads();

    stageBh(S + oBR,         ufT,                 128, tid, 256);
    stageBh(S + oBR + 16384, ufT + 16384,         128, tid, 256);
    stageBh(S + oBZ,         ufT + 64,            128, tid, 256);
    stageBh(S + oBZ + 16384, ufT + 16384 + 64,    128, tid, 256);
    cpcommit();

    const int lr = lane >> 2, lc = 2 * (lane & 3);
#pragma unroll
    for (int f = 0; f < 8; f++) {
        int colb = n0 + (f & 3) * 8 + lc;
#pragma unroll
        for (int hp = 0; hp < 2; hp++) {
            int row = m0 + (f >> 2) * 16 + lr + hp * 8;
            __half H0, L0, H1, L1;
            wsplit(acc[f][hp * 2], H0, L0); wsplit(acc[f][hp * 2 + 1], H1, L1);
            u32 aoff = (u32)row * 256u + (u32)((((colb >> 3) ^ (row & 7)) << 4)) + (colb & 7) * 2;
            *(__half2*)(dsm + oAH + aoff) = __halves2half2(H0, H1);
            *(__half2*)(dsm + oAL + aoff) = __halves2half2(L0, L1);
        }
    }
    cpwait0(); __syncthreads();

    zacc8(acc);
    for (int kc = 0; kc < 4; kc++)
        kstep128h(acc, S + oAH, S + oAL, S + oBR, S + oBR + 16384, m0, n0, lane, kc, kc);
    __syncthreads();
    stageBh(S + oBR,         uaT,         128, tid, 256);
    stageBh(S + oBR + 16384, uaT + 16384, 128, tid, 256);
    cpcommit();
    for (int kc = 4; kc < 8; kc++)
        kstep128h(acc, S + oAH, S + oAL, S + oBZ, S + oBZ + 16384, m0, n0, lane, kc, kc - 4);
    __syncthreads();
    stage128(S + oAH, pah + (size_t)row0 * 128, 64, tid, 256);
    stage128(S + oAL, pal + (size_t)row0 * 128, 64, tid, 256);
    stageBh(S + oBZ,         uaT + 64,         128, tid, 256);
    stageBh(S + oBZ + 16384, uaT + 16384 + 64, 128, tid, 256);
    cpcommit(); cpwait0(); __syncthreads();

    for (int kc = 0; kc < 4; kc++)
        kstep128h(acc, S + oAH, S + oAL, S + oBR, S + oBR + 16384, m0, n0, lane, kc, kc);
    for (int kc = 4; kc < 8; kc++)
        kstep128h(acc, S + oAH, S + oAL, S + oBZ, S + oBZ + 16384, m0, n0, lane, kc, kc - 4);

#pragma unroll
    for (int f = 0; f < 8; f++) {
        int colb = n0 + (f & 3) * 8 + lc;
        float b0 = __ldg(ufb + colb) + __ldg(uab + colb);
        float b1 = __ldg(ufb + colb + 1) + __ldg(uab + colb + 1);
#pragma unroll
        for (int hp = 0; hp < 2; hp++) {
            int row = m0 + (f >> 2) * 16 + lr + hp * 8;
            float o0 = ftanh(acc[f][hp * 2] + b0);
            float o1 = ftanh(acc[f][hp * 2 + 1] + b1);
            __half H0, L0, H1, L1;
            wsplit(o0, H0, L0); wsplit(o1, H1, L1);
            size_t go = (size_t)(row0 + row) * 128 + colb;
            *(__half2*)(oh + go) = __halves2half2(H0, H1);
            *(__half2*)(ol + go) = __halves2half2(L0, L1);
        }
    }
}

// ===================== leaf node =====================
#define nAH 0
#define nAL 16384
#define nBH 32768
#define nBL 40960
#define nPR 49152
#define NODE_DS 57344

__global__ __launch_bounds__(256, 2)
void node_k(const __half* __restrict__ hh, const __half* __restrict__ hl,
            const __half* __restrict__ h2oT, const float* __restrict__ b,
            float* __restrict__ pred, __half* __restrict__ ph, __half* __restrict__ pl)
{
    extern __shared__ char dsm[];
    const u32 S = smaddr(dsm);
    const int tid = threadIdx.x, lane = tid & 31, wid = tid >> 5;
    const int row0 = blockIdx.x * 64;

    stage128(S + nAH, hh + (size_t)row0 * 128, 64, tid, 256);
    stage128(S + nAL, hl + (size_t)row0 * 128, 64, tid, 256);
    stageBh(S + nBH, h2oT, 32, tid, 256);
    stageBh(S + nBH + 4096, h2oT + 64, 32, tid, 256);
    stageBh(S + nBL, h2oT + 4096, 32, tid, 256);
    stageBh(S + nBL + 4096, h2oT + 4096 + 64, 32, tid, 256);
    cpcommit(); cpwait0(); __syncthreads();

    {
        const int pm0 = (wid & 3) * 16, Gp = wid >> 2;
        float a4[2][4];
#pragma unroll
        for (int f = 0; f < 2; f++)
#pragma unroll
            for (int i = 0; i < 4; i++) a4[f][i] = 0.0f;
        for (int kc = 0; kc < 8; kc++) {
            int half = kc >> 2, kb = kc & 3;
            u32 ahr[4], alr[4], bh[4], bl[4];
            ldmA128(ahr, S + nAH, pm0, lane, kc);
            ldmA128(alr, S + nAL, pm0, lane, kc);
            ldmBh(bh, S + nBH + half * 4096, Gp * 16, lane, kb);
            ldmBh(bl, S + nBL + half * 4096, Gp * 16, lane, kb);
            mmaf(a4[0], ahr, bh);  mmaf(a4[1], ahr, bh + 2);
            mmaf(a4[0], ahr, bl);  mmaf(a4[1], ahr, bl + 2);
            mmaf(a4[0], alr, bh);  mmaf(a4[1], alr, bh + 2);
        }
        const int lr = lane >> 2, lc = 2 * (lane & 3);
#pragma unroll
        for (int f = 0; f < 2; f++)
#pragma unroll
            for (int i = 0; i < 4; i++) {
                int row = pm0 + lr + (i >> 1) * 8;
                int col = Gp * 16 + f * 8 + lc + (i & 1);
                *(float*)(dsm + nPR + (row * 32 + col) * 4) = a4[f][i] + __ldg(b + col);
            }
    }
    __syncthreads();
    if (tid < 64) {
        int row = tid;
        const float* pr = (const float*)(dsm + nPR + row * 128);
        float v[32], mx = -1e30f;
#pragma unroll
        for (int i = 0; i < 32; i++) { v[i] = pr[i]; mx = fmaxf(mx, v[i]); }
        float e[32], sum = 0.0f;
#pragma unroll
        for (int i = 0; i < 32; i++) { e[i] = __expf(v[i] - mx); sum += e[i]; }
        float inv = __fdividef(1.0f, sum);
        size_t go = (size_t)(row0 + row) * 32;
        float4* pg = (float4*)(pred + go);
#pragma unroll
        for (int q = 0; q < 8; q++)
            pg[q] = make_float4(v[4 * q], v[4 * q + 1], v[4 * q + 2], v[4 * q + 3]);
#pragma unroll
        for (int j = 0; j < 16; j++) {
            float p0 = e[2 * j] * inv, p1 = e[2 * j + 1] * inv;
            __half H0, L0, H1, L1;
            wsplit(p0, H0, L0); wsplit(p1, H1, L1);
            *(__half2*)(ph + go + 2 * j) = __halves2half2(H0, H1);
            *(__half2*)(pl + go + 2 * j) = __halves2half2(L0, L1);
        }
    }
}

// ===================== host: preorder with side-stream grucomb overlap =====================
namespace {

#define PL ((size_t)BATCH * HD)
#define PP ((size_t)BATCH * OD)

struct LCtx {
    const __half* wt;
    const float *h2o_b;
    const float *anc_bi, *anc_bh, *frat_bi, *frat_bh;
    const float *ua_b, *uf_b;
    __half *hAh, *hAl, *prh, *prl;
    float* out;
    int idx;
    cudaStream_t side;
    cudaEvent_t* ev;
    int evn;
};

// returns an event recorded right after this node's root kernel (probs ready)
cudaEvent_t rec(LCtx& c, int L, int d, int par)
{
    const size_t hin = (size_t)(L * 2 + par) * PL;
    const size_t pL = (size_t)L * PP;

    if (d == 0) {
        node_k<<<BATCH / 64, 256, NODE_DS>>>(c.hAh + hin, c.hAl + hin,
                                             c.wt + W_H2O, c.h2o_b,
                                             c.out + (size_t)c.idx * BATCH * OD,
                                             c.prh + pL, c.prl + pL);
        c.idx++;
        cudaEvent_t e = c.ev[c.evn++];
        cudaEventRecord(e, 0);
        return e;
    }

    const size_t h0 = (size_t)((L + 1) * 2 + 0) * PL;   // first-child hidden (h_ai)
    const size_t h1 = (size_t)((L + 1) * 2 + 1) * PL;   // second-child hidden
    const size_t pL1 = (size_t)(L + 1) * PP;

    nodegru_k<<<BATCH / 64, 256, FUSE_DS>>>(c.hAh + hin, c.hAl + hin,
                                            c.wt + W_H2O, c.h2o_b,
                                            c.out + (size_t)c.idx * BATCH * OD,
                                            c.prh + pL, c.prl + pL,
                                            c.wt + W_ANC_WH, c.wt + W_ANC_WI,
                                            c.anc_bi, c.anc_bh,
                                            c.hAh + h0, c.hAl + h0);
    c.idx++;
    cudaEvent_t e_self = c.ev[c.evn++];
    cudaEventRecord(e_self, 0);

    // first child subtree (enqueued on main stream)
    cudaEvent_t e_c1 = rec(c, L + 1, d - 1, 0);

    // grucomb on side stream: needs only child1's root kernel (probs + h_ai read-only)
    cudaStreamWaitEvent(c.side, e_c1, 0);
    grucomb_k<<<BATCH / 64, 256, FUSE_DS, c.side>>>(c.prh + pL1, c.prl + pL1,
                                                    c.hAh + h0, c.hAl + h0,
                                                    c.wt + W_FRAT_WH, c.wt + W_FRAT_WI,
                                                    c.frat_bi, c.frat_bh,
                                                    c.hAh + hin, c.hAl + hin,
                                                    c.wt + W_UF, c.wt + W_UA,
                                                    c.uf_b, c.ua_b,
                                                    c.hAh + h1, c.hAl + h1);
    cudaEvent_t e_gc = c.ev[c.evn++];
    cudaEventRecord(e_gc, c.side);

    // second child subtree waits for grucomb's hidden
    cudaStreamWaitEvent(0, e_gc, 0);
    rec(c, L + 1, d - 1, 1);

    return e_self;
}

} // namespace

extern "C" void kernel_launch(void* const* d_in, const int* in_sizes, int n_in,
                              void* d_out, int out_size)
{
    const float* z       = (const float*)d_in[0];
    const float* z2h_w   = (const float*)d_in[1];
    const float* z2h_b   = (const float*)d_in[2];
    const float* h2o_w   = (const float*)d_in[3];
    const float* h2o_b   = (const float*)d_in[4];
    const float* anc_wi  = (const float*)d_in[5];
    const float* anc_wh  = (const float*)d_in[6];
    const float* anc_bi  = (const float*)d_in[7];
    const float* anc_bh  = (const float*)d_in[8];
    const float* frat_wi = (const float*)d_in[9];
    const float* frat_wh = (const float*)d_in[10];
    const float* frat_bi = (const float*)d_in[11];
    const float* frat_bh = (const float*)d_in[12];
    const float* ua_w    = (const float*)d_in[13];
    const float* ua_b    = (const float*)d_in[14];
    const float* uf_w    = (const float*)d_in[15];
    const float* uf_b    = (const float*)d_in[16];

    static cudaStream_t s_side = nullptr;
    static cudaEvent_t s_ev[128];
    static bool s_init = false;
    if (!s_init) {
        cudaStreamCreateWithFlags(&s_side, cudaStreamNonBlocking);
        for (int i = 0; i < 128; i++)
            cudaEventCreateWithFlags(&s_ev[i], cudaEventDisableTiming);
        cudaFuncSetAttribute(nodegru_k, cudaFuncAttributeMaxDynamicSharedMemorySize, FUSE_DS);
        cudaFuncSetAttribute(grucomb_k, cudaFuncAttributeMaxDynamicSharedMemorySize, FUSE_DS);
        cudaFuncSetAttribute(node_k,    cudaFuncAttributeMaxDynamicSharedMemorySize, NODE_DS);
        s_init = true;
    }

    __half *wt, *hAh, *hAl, *prh, *prl;
    cudaGetSymbolAddress((void**)&wt, g_wt);
    cudaGetSymbolAddress((void**)&hAh, g_hAh);
    cudaGetSymbolAddress((void**)&hAl, g_hAl);
    cudaGetSymbolAddress((void**)&prh, g_prh);
    cudaGetSymbolAddress((void**)&prl, g_prl);

    k_prep<<<128, 256>>>(anc_wi, anc_wh, frat_wi, frat_wh, uf_w, ua_w, h2o_w);
    init_k<<<BATCH / 16, 128>>>(z, z2h_w, z2h_b, hAh, hAl);   // writes slot (0,0)

    LCtx c;
    c.wt = wt; c.h2o_b = h2o_b;
    c.anc_bi = anc_bi; c.anc_bh = anc_bh;
    c.frat_bi = frat_bi; c.frat_bh = frat_bh;
    c.ua_b = ua_b; c.uf_b = uf_b;
    c.hAh = hAh; c.hAl = hAl;
    c.prh = prh; c.prl = prl;
    c.out = (float*)d_out;
    c.idx = 0;
    c.side = s_side;
    c.ev = s_ev;
    c.evn = 0;

    rec(c, 0, DEPTH, 0);
}

// round 16
// speedup vs baseline: 1.1638x; 1.1584x over previous
#include <cuda_runtime.h>
#include <cuda_fp16.h>
#include <cstdint>

#define BATCH 32768
#define HD 128
#define OD 32
#define DEPTH 5
#define NNODES 63
#define NW 11
typedef uint32_t u32;

// ---- batched-launch id lists (passed by value) ----
struct Ids { int v[16]; };
struct Gc  { int p[8]; int l[8]; int r[8]; };

// ---- weight tile offsets in g_wt (halves) ----
#define W_ANC_WH  0
#define W_FRAT_WH 98304
#define W_ANC_WI  196608
#define W_FRAT_WI 221184
#define W_UF      245760
#define W_UA      278528
#define W_H2O     311296
__device__ __half g_wt[319488];

// per-node buffers (preorder id 0..62)
__device__ __half g_hAh[NNODES][BATCH * HD];
__device__ __half g_hAl[NNODES][BATCH * HD];
__device__ __half g_prh[NNODES][BATCH * OD];
__device__ __half g_prl[NNODES][BATCH * OD];

#define PL ((size_t)BATCH * HD)
#define PP ((size_t)BATCH * OD)

// ===================== helpers =====================
__device__ __forceinline__ u32 smaddr(const void* p) {
    u32 a;
    asm("{ .reg .u64 t; cvta.to.shared.u64 t, %1; cvt.u32.u64 %0, t; }" : "=r"(a) : "l"(p));
    return a;
}
__device__ __forceinline__ void cpa16(u32 d, const void* s) {
    asm volatile("cp.async.cg.shared.global [%0], [%1], 16;" :: "r"(d), "l"(s) : "memory");
}
__device__ __forceinline__ void cpcommit() {
    asm volatile("cp.async.commit_group;" ::: "memory");
}
__device__ __forceinline__ void cpwait0() {
    asm volatile("cp.async.wait_group 0;" ::: "memory");
}
__device__ __forceinline__ void ldm4(u32* r, u32 a) {
    asm volatile("ldmatrix.sync.aligned.m8n8.x4.shared.b16 {%0,%1,%2,%3}, [%4];"
                 : "=r"(r[0]), "=r"(r[1]), "=r"(r[2]), "=r"(r[3]) : "r"(a));
}
__device__ __forceinline__ void mmaf(float* c, const u32* a, const u32* b) {
    asm volatile(
        "mma.sync.aligned.m16n8k16.row.col.f32.f16.f16.f32 "
        "{%0,%1,%2,%3},{%4,%5,%6,%7},{%8,%9},{%0,%1,%2,%3};"
        : "+f"(c[0]), "+f"(c[1]), "+f"(c[2]), "+f"(c[3])
        : "r"(a[0]), "r"(a[1]), "r"(a[2]), "r"(a[3]), "r"(b[0]), "r"(b[1]));
}
__device__ __forceinline__ float fsig(float x)  { return __fdividef(1.0f, 1.0f + __expf(-x)); }
__device__ __forceinline__ float ftanh(float x) { float u = __expf(2.0f * x); return 1.0f - __fdividef(2.0f, u + 1.0f); }
__device__ __forceinline__ void wsplit(float v, __half& h, __half& l) {
    h = __float2half_rn(v);
    l = __float2half_rn(v - __half2float(h));
}

// ---- ldmatrix addressing ----
__device__ __forceinline__ void ldmA128(u32* r, u32 base, int m0, int lane, int kc) {
    int row = m0 + (lane & 15), c16 = 2 * kc + (lane >> 4);
    ldm4(r, base + (u32)row * 256u + (u32)((c16 ^ (row & 7)) << 4));
}
__device__ __forceinline__ void ldmBh(u32* r, u32 base, int n0, int lane, int kc) {
    int row = n0 + (lane & 7) + ((lane >> 4) << 3), c8 = 2 * kc + ((lane >> 3) & 1);
    ldm4(r, base + (u32)row * 128u + (u32)((c8 ^ (row & 7)) << 4));
}
__device__ __forceinline__ void ldmA32(u32* r, u32 base, int m0, int lane, int kc) {
    int row = m0 + (lane & 15), c4 = 2 * kc + (lane >> 4);
    ldm4(r, base + (u32)row * 64u + (u32)((c4 ^ (row & 3)) << 4));
}
__device__ __forceinline__ void ldmB32(u32* r, u32 base, int n0, int lane, int kc) {
    int row = n0 + (lane & 7) + ((lane >> 4) << 3), c4 = 2 * kc + ((lane >> 3) & 1);
    ldm4(r, base + (u32)row * 64u + (u32)((c4 ^ (row & 3)) << 4));
}

// ---- single-gate 32x32 kstep ----
__device__ __forceinline__ void kstep128h(float (*acc)[4], u32 AH, u32 AL, u32 BH, u32 BL,
                                          int m0, int n0, int lane, int kcA, int kcB) {
    u32 a[4][4];
    ldmA128(a[0], AH, m0, lane, kcA);      ldmA128(a[1], AH, m0 + 16, lane, kcA);
    ldmA128(a[2], AL, m0, lane, kcA);      ldmA128(a[3], AL, m0 + 16, lane, kcA);
#pragma unroll
    for (int G = 0; G < 2; G++) {
        u32 bh[4], bl[4];
        ldmBh(bh, BH, n0 + G * 16, lane, kcB);
        ldmBh(bl, BL, n0 + G * 16, lane, kcB);
#pragma unroll
        for (int mf = 0; mf < 2; mf++) {
            float* c0 = acc[mf * 4 + G * 2];
            float* c1 = acc[mf * 4 + G * 2 + 1];
            mmaf(c0, a[mf], bh);     mmaf(c1, a[mf], bh + 2);
            mmaf(c0, a[mf], bl);     mmaf(c1, a[mf], bl + 2);
            mmaf(c0, a[2 + mf], bh); mmaf(c1, a[2 + mf], bh + 2);
        }
    }
}
__device__ __forceinline__ void kstep32w(float (*acc)[4], u32 AH, u32 AL, u32 BH, u32 BL,
                                         int m0, int n0, int lane, int kc) {
    u32 a[4][4];
    ldmA32(a[0], AH, m0, lane, kc);      ldmA32(a[1], AH, m0 + 16, lane, kc);
    ldmA32(a[2], AL, m0, lane, kc);      ldmA32(a[3], AL, m0 + 16, lane, kc);
#pragma unroll
    for (int G = 0; G < 2; G++) {
        u32 bh[4], bl[4];
        ldmB32(bh, BH, n0 + G * 16, lane, kc);
        ldmB32(bl, BL, n0 + G * 16, lane, kc);
#pragma unroll
        for (int mf = 0; mf < 2; mf++) {
            float* c0 = acc[mf * 4 + G * 2];
            float* c1 = acc[mf * 4 + G * 2 + 1];
            mmaf(c0, a[mf], bh);     mmaf(c1, a[mf], bh + 2);
            mmaf(c0, a[mf], bl);     mmaf(c1, a[mf], bl + 2);
            mmaf(c0, a[2 + mf], bh); mmaf(c1, a[2 + mf], bh + 2);
        }
    }
}
// ---- dual-gate ksteps ----
__device__ __forceinline__ void kdual128(float (*aR)[4], float (*aZ)[4], u32 AH, u32 AL,
                                         u32 BRh, u32 BRl, u32 BZh, u32 BZl,
                                         int m0, int n0, int lane, int kcA, int kcB) {
    u32 a[4][4];
    ldmA128(a[0], AH, m0, lane, kcA);      ldmA128(a[1], AH, m0 + 16, lane, kcA);
    ldmA128(a[2], AL, m0, lane, kcA);      ldmA128(a[3], AL, m0 + 16, lane, kcA);
    {
        u32 bh[4], bl[4];
        ldmBh(bh, BRh, n0, lane, kcB);  ldmBh(bl, BRl, n0, lane, kcB);
#pragma unroll
        for (int mf = 0; mf < 2; mf++) {
            float* c0 = aR[mf * 4]; float* c1 = aR[mf * 4 + 1];
            mmaf(c0, a[mf], bh);     mmaf(c1, a[mf], bh + 2);
            mmaf(c0, a[mf], bl);     mmaf(c1, a[mf], bl + 2);
            mmaf(c0, a[2 + mf], bh); mmaf(c1, a[2 + mf], bh + 2);
        }
        ldmBh(bh, BRh, n0 + 16, lane, kcB);  ldmBh(bl, BRl, n0 + 16, lane, kcB);
#pragma unroll
        for (int mf = 0; mf < 2; mf++) {
            float* c0 = aR[mf * 4 + 2]; float* c1 = aR[mf * 4 + 3];
            mmaf(c0, a[mf], bh);     mmaf(c1, a[mf], bh + 2);
            mmaf(c0, a[mf], bl);     mmaf(c1, a[mf], bl + 2);
            mmaf(c0, a[2 + mf], bh); mmaf(c1, a[2 + mf], bh + 2);
        }
    }
    {
        u32 bh[4], bl[4];
        ldmBh(bh, BZh, n0, lane, kcB);  ldmBh(bl, BZl, n0, lane, kcB);
#pragma unroll
        for (int mf = 0; mf < 2; mf++) {
            float* c0 = aZ[mf * 4]; float* c1 = aZ[mf * 4 + 1];
            mmaf(c0, a[mf], bh);     mmaf(c1, a[mf], bh + 2);
            mmaf(c0, a[mf], bl);     mmaf(c1, a[mf], bl + 2);
            mmaf(c0, a[2 + mf], bh); mmaf(c1, a[2 + mf], bh + 2);
        }
        ldmBh(bh, BZh, n0 + 16, lane, kcB);  ldmBh(bl, BZl, n0 + 16, lane, kcB);
#pragma unroll
        for (int mf = 0; mf < 2; mf++) {
            float* c0 = aZ[mf * 4 + 2]; float* c1 = aZ[mf * 4 + 3];
            mmaf(c0, a[mf], bh);     mmaf(c1, a[mf], bh + 2);
            mmaf(c0, a[mf], bl);     mmaf(c1, a[mf], bl + 2);
            mmaf(c0, a[2 + mf], bh); mmaf(c1, a[2 + mf], bh + 2);
        }
    }
}
__device__ __forceinline__ void kdual32(float (*aR)[4], float (*aZ)[4], u32 AH, u32 AL,
                                        u32 BRh, u32 BRl, u32 BZh, u32 BZl,
                                        int m0, int n0, int lane, int kc) {
    u32 a[4][4];
    ldmA32(a[0], AH, m0, lane, kc);      ldmA32(a[1], AH, m0 + 16, lane, kc);
    ldmA32(a[2], AL, m0, lane, kc);      ldmA32(a[3], AL, m0 + 16, lane, kc);
#pragma unroll
    for (int G = 0; G < 2; G++) {
        {
            u32 bh[4], bl[4];
            ldmB32(bh, BRh, n0 + G * 16, lane, kc);
            ldmB32(bl, BRl, n0 + G * 16, lane, kc);
#pragma unroll
            for (int mf = 0; mf < 2; mf++) {
                float* c0 = aR[mf * 4 + G * 2];
                float* c1 = aR[mf * 4 + G * 2 + 1];
                mmaf(c0, a[mf], bh);     mmaf(c1, a[mf], bh + 2);
                mmaf(c0, a[mf], bl);     mmaf(c1, a[mf], bl + 2);
                mmaf(c0, a[2 + mf], bh); mmaf(c1, a[2 + mf], bh + 2);
            }
        }
        {
            u32 bh[4], bl[4];
            ldmB32(bh, BZh, n0 + G * 16, lane, kc);
            ldmB32(bl, BZl, n0 + G * 16, lane, kc);
#pragma unroll
            for (int mf = 0; mf < 2; mf++) {
                float* c0 = aZ[mf * 4 + G * 2];
                float* c1 = aZ[mf * 4 + G * 2 + 1];
                mmaf(c0, a[mf], bh);     mmaf(c1, a[mf], bh + 2);
                mmaf(c0, a[mf], bl);     mmaf(c1, a[mf], bl + 2);
                mmaf(c0, a[2 + mf], bh); mmaf(c1, a[2 + mf], bh + 2);
            }
        }
    }
}
__device__ __forceinline__ void zacc8(float (*acc)[4]) {
#pragma unroll
    for (int f = 0; f < 8; f++)
#pragma unroll
        for (int i = 0; i < 4; i++) acc[f][i] = 0.0f;
}

// ---- staging ----
__device__ __forceinline__ void stage128(u32 dst, const __half* src, int rows, int tid, int nt) {
    for (int i = tid; i < rows * 16; i += nt) {
        int r = i >> 4, c = i & 15;
        cpa16(dst + (u32)r * 256u + (u32)((c ^ (r & 7)) << 4), src + (size_t)r * 128 + c * 8);
    }
}
__device__ __forceinline__ void stageBh(u32 dst, const __half* src, int rows, int tid, int nt) {
    for (int i = tid; i < rows * 8; i += nt) {
        int r = i >> 3, c = i & 7;
        cpa16(dst + (u32)r * 128u + (u32)((c ^ (r & 7)) << 4), src + (size_t)r * 128 + c * 8);
    }
}
__device__ __forceinline__ void stage32s(u32 dst, const __half* src, int rows, int tid, int nt) {
    for (int i = tid; i < rows * 4; i += nt) {
        int r = i >> 2, c = i & 3;
        cpa16(dst + (u32)r * 64u + (u32)((c ^ (r & 3)) << 4), src + (size_t)r * 32 + c * 8);
    }
}

// ===================== prep =====================
__global__ void k_prep(const float* __restrict__ anc_wi, const float* __restrict__ anc_wh,
                       const float* __restrict__ frat_wi, const float* __restrict__ frat_wh,
                       const float* __restrict__ uf_w, const float* __restrict__ ua_w,
                       const float* __restrict__ h2o_w)
{
    int t = blockIdx.x * blockDim.x + threadIdx.x, NT = gridDim.x * blockDim.x;
    for (int i = t; i < 3 * 16384; i += NT) {
        int g = i >> 14, rem = i & 16383, k = rem >> 7, n = rem & 127;
        int d = g * 32768 + n * 128 + k;
        __half h, l;
        wsplit(anc_wh[i], h, l);  g_wt[W_ANC_WH + d] = h;  g_wt[W_ANC_WH + d + 16384] = l;
        wsplit(frat_wh[i], h, l); g_wt[W_FRAT_WH + d] = h; g_wt[W_FRAT_WH + d + 16384] = l;
    }
    for (int i = t; i < 3 * 4096; i += NT) {
        int g = i >> 12, rem = i & 4095, k = rem >> 7, n = rem & 127;
        int d = g * 8192 + n * 32 + k;
        __half h, l;
        wsplit(anc_wi[i], h, l);  g_wt[W_ANC_WI + d] = h;  g_wt[W_ANC_WI + d + 4096] = l;
        wsplit(frat_wi[i], h, l); g_wt[W_FRAT_WI + d] = h; g_wt[W_FRAT_WI + d + 4096] = l;
    }
    for (int i = t; i < 16384; i += NT) {
        int k = i >> 7, n = i & 127, d = n * 128 + k;
        __half h, l;
        wsplit(uf_w[i], h, l); g_wt[W_UF + d] = h; g_wt[W_UF + d + 16384] = l;
        wsplit(ua_w[i], h, l); g_wt[W_UA + d] = h; g_wt[W_UA + d + 16384] = l;
    }
    for (int i = t; i < 4096; i += NT) {
        int k = i >> 5, n = i & 31, d = n * 128 + k;
        __half h, l;
        wsplit(h2o_w[i], h, l); g_wt[W_H2O + d] = h; g_wt[W_H2O + d + 4096] = l;
    }
}

// ===================== init =====================
__global__ __launch_bounds__(128, 4)
void init_k(const float* __restrict__ z, const float* __restrict__ w,
            const float* __restrict__ b, __half* __restrict__ oh, __half* __restrict__ ol)
{
    const int g = threadIdx.x;
    const int row0 = blockIdx.x * 16;
    __shared__ float s[16][HD];
    for (int r = 0; r < 16; r++) s[r][g] = z[(size_t)(row0 + r) * HD + g];
    __syncthreads();
    float a[16];
#pragma unroll
    for (int r = 0; r < 16; r++) a[r] = 0.0f;
    for (int j = 0; j < HD; j++) {
        float wv = __ldg(w + (size_t)j * HD + g);
#pragma unroll
        for (int r = 0; r < 16; r++) a[r] += s[r][j] * wv;
    }
    float bg = __ldg(b + g);
#pragma unroll
    for (int r = 0; r < 16; r++) {
        __half h, l; wsplit(a[r] + bg, h, l);
        size_t o = (size_t)(row0 + r) * HD + g;
        oh[o] = h; ol[o] = l;
    }
}

// ===================== fused-kernel SMEM layout =====================
#define oAH  0
#define oAL  16384
#define oAXH 32768
#define oAXL 36864
#define oBR  40960
#define oBZ  73728
#define oBIA 106496
#define FUSE_DS 108544

__device__ __forceinline__ void load_bias(char* dsm, const float* bi, const float* bhp, int tid) {
    if (tid < 128) {
        float4 bv = make_float4(__ldg(bi + tid) + __ldg(bhp + tid),
                                __ldg(bi + 128 + tid) + __ldg(bhp + 128 + tid),
                                __ldg(bhp + 256 + tid), __ldg(bi + 256 + tid));
        *(float4*)(dsm + oBIA + tid * 16) = bv;
    }
}

// ---- full GRU body (R12, unchanged) ----
__device__ __forceinline__ void gru_body(char* dsm, u32 S, const __half* whT, const __half* wiT,
                                         int tid, int lane, int m0, int n0, float (*acc)[4])
{
    const int lr = lane >> 2, lc = 2 * (lane & 3);
    const float Q = 1.0f / 65535.0f;
    u32 rq[16], zq[16];

    cpwait0(); __syncthreads();

    {
        float accZ[8][4];
        zacc8(acc); zacc8(accZ);
        for (int kc = 0; kc < 4; kc++)
            kdual128(acc, accZ, S + oAH, S + oAL,
                     S + oBR, S + oBR + 16384, S + oBZ, S + oBZ + 16384,
                     m0, n0, lane, kc, kc);
        __syncthreads();
        stageBh(S + oBR,         whT + 64,                 128, tid, 256);
        stageBh(S + oBR + 16384, whT + 16384 + 64,         128, tid, 256);
        stageBh(S + oBZ,         whT + 32768 + 64,         128, tid, 256);
        stageBh(S + oBZ + 16384, whT + 49152 + 64,         128, tid, 256);
        cpcommit(); cpwait0(); __syncthreads();
        for (int kc = 4; kc < 8; kc++)
            kdual128(acc, accZ, S + oAH, S + oAL,
                     S + oBR, S + oBR + 16384, S + oBZ, S + oBZ + 16384,
                     m0, n0, lane, kc, kc - 4);
        __syncthreads();
        stage32s(S + oBR,        wiT,         128, tid, 256);
        stage32s(S + oBR + 8192, wiT + 4096,  128, tid, 256);
        stage32s(S + oBZ,        wiT + 8192,  128, tid, 256);
        stage32s(S + oBZ + 8192, wiT + 12288, 128, tid, 256);
        cpcommit(); cpwait0(); __syncthreads();
        for (int kc = 0; kc < 2; kc++)
            kdual32(acc, accZ, S + oAXH, S + oAXL,
                    S + oBR, S + oBR + 8192, S + oBZ, S + oBZ + 8192,
                    m0, n0, lane, kc);
#pragma unroll
        for (int f = 0; f < 8; f++) {
            int colb = n0 + (f & 3) * 8 + lc;
            const float* bp = (const float*)(dsm + oBIA + colb * 16);
            const float* bq = (const float*)(dsm + oBIA + (colb + 1) * 16);
            rq[2 * f]     = (u32)(fsig(acc[f][0] + bp[0]) * 65535.f + 0.5f)
                          | ((u32)(fsig(acc[f][1] + bq[0]) * 65535.f + 0.5f) << 16);
            rq[2 * f + 1] = (u32)(fsig(acc[f][2] + bp[0]) * 65535.f + 0.5f)
                          | ((u32)(fsig(acc[f][3] + bq[0]) * 65535.f + 0.5f) << 16);
            zq[2 * f]     = (u32)(fsig(accZ[f][0] + bp[1]) * 65535.f + 0.5f)
                          | ((u32)(fsig(accZ[f][1] + bq[1]) * 65535.f + 0.5f) << 16);
            zq[2 * f + 1] = (u32)(fsig(accZ[f][2] + bp[1]) * 65535.f + 0.5f)
                          | ((u32)(fsig(accZ[f][3] + bq[1]) * 65535.f + 0.5f) << 16);
        }
    }
    __syncthreads();

    stageBh(S + oBR,         whT + 65536,         128, tid, 256);
    stageBh(S + oBR + 16384, whT + 65536 + 16384, 128, tid, 256);
    stage32s(S + oBZ,        wiT + 16384,         128, tid, 256);
    stage32s(S + oBZ + 8192, wiT + 20480,         128, tid, 256);
    cpcommit(); cpwait0(); __syncthreads();

    zacc8(acc);
    for (int kc = 0; kc < 4; kc++)
        kstep128h(acc, S + oAH, S + oAL, S + oBR, S + oBR + 16384, m0, n0, lane, kc, kc);
    __syncthreads();
    stageBh(S + oBR,         whT + 65536 + 64,         128, tid, 256);
    stageBh(S + oBR + 16384, whT + 65536 + 16384 + 64, 128, tid, 256);
    cpcommit(); cpwait0(); __syncthreads();
    for (int kc = 4; kc < 8; kc++)
        kstep128h(acc, S + oAH, S + oAL, S + oBR, S + oBR + 16384, m0, n0, lane, kc, kc - 4);
#pragma unroll
    for (int f = 0; f < 8; f++) {
        int colb = n0 + (f & 3) * 8 + lc;
        const float* bp = (const float*)(dsm + oBIA + colb * 16);
        const float* bq = (const float*)(dsm + oBIA + (colb + 1) * 16);
#pragma unroll
        for (int hp = 0; hp < 2; hp++) {
            u32 rv = rq[2 * f + hp];
            acc[f][hp * 2]     = (float)(rv & 0xffffu) * Q * (acc[f][hp * 2]     + bp[2]) + bp[3];
            acc[f][hp * 2 + 1] = (float)(rv >> 16)     * Q * (acc[f][hp * 2 + 1] + bq[2]) + bq[3];
        }
    }
    for (int kc = 0; kc < 2; kc++)
        kstep32w(acc, S + oAXH, S + oAXL, S + oBZ, S + oBZ + 8192, m0, n0, lane, kc);

#pragma unroll
    for (int f = 0; f < 8; f++) {
        int colb = n0 + (f & 3) * 8 + lc;
#pragma unroll
        for (int hp = 0; hp < 2; hp++) {
            int row = m0 + (f >> 2) * 16 + lr + hp * 8;
            u32 zv = zq[2 * f + hp];
            float zz0 = (float)(zv & 0xffffu) * Q, zz1 = (float)(zv >> 16) * Q;
            float nn0 = ftanh(acc[f][hp * 2]), nn1 = ftanh(acc[f][hp * 2 + 1]);
            u32 aoff = (u32)row * 256u + (u32)((((colb >> 3) ^ (row & 7)) << 4)) + (colb & 7) * 2;
            __half2 hhv = *(__half2*)(dsm + oAH + aoff);
            __half2 hlv = *(__half2*)(dsm + oAL + aoff);
            float h0 = __half2float(__low2half(hhv)) + __half2float(__low2half(hlv));
            float h1 = __half2float(__high2half(hhv)) + __half2float(__high2half(hlv));
            acc[f][hp * 2]     = (1.0f - zz0) * nn0 + zz0 * h0;
            acc[f][hp * 2 + 1] = (1.0f - zz1) * nn1 + zz1 * h1;
        }
    }
}

// ===================== batched nodegru (internal nodes of one wave) =====================
__global__ __launch_bounds__(256, 2)
void nodegru_b(const __half* __restrict__ h2oT, const float* __restrict__ h2ob,
               float* __restrict__ out,
               const __half* __restrict__ whT, const __half* __restrict__ wiT,
               const float* __restrict__ bi, const float* __restrict__ bhp,
               __half* __restrict__ hAh, __half* __restrict__ hAl,
               __half* __restrict__ prh, __half* __restrict__ prl,
               Ids lst)
{
    extern __shared__ char dsm[];
    const u32 S = smaddr(dsm);
    const int tid = threadIdx.x, lane = tid & 31, wid = tid >> 5;
    const int id = lst.v[blockIdx.x >> 9];
    const int row0 = (blockIdx.x & 511) * 64;
    const int m0 = (wid & 1) * 32, n0 = (wid >> 1) * 32;

    const __half* hh = hAh + (size_t)id * PL;
    const __half* hl = hAl + (size_t)id * PL;
    float* pred = out + (size_t)id * PP;
    __half* ph = prh + (size_t)id * PP;
    __half* pl = prl + (size_t)id * PP;
    __half* oh = hAh + (size_t)(id + 1) * PL;
    __half* ol = hAl + (size_t)(id + 1) * PL;

    load_bias(dsm, bi, bhp, tid);
    stage128(S + oAH, hh + (size_t)row0 * 128, 64, tid, 256);
    stage128(S + oAL, hl + (size_t)row0 * 128, 64, tid, 256);
    stageBh(S + oBR,         h2oT,             32, tid, 256);
    stageBh(S + oBR + 4096,  h2oT + 64,        32, tid, 256);
    stageBh(S + oBR + 16384, h2oT + 4096,      32, tid, 256);
    stageBh(S + oBR + 20480, h2oT + 4096 + 64, 32, tid, 256);
    cpcommit(); cpwait0(); __syncthreads();

    {
        const int pm0 = (wid & 3) * 16, Gp = wid >> 2;
        float a4[2][4];
#pragma unroll
        for (int f = 0; f < 2; f++)
#pragma unroll
            for (int i = 0; i < 4; i++) a4[f][i] = 0.0f;
        for (int kc = 0; kc < 8; kc++) {
            int half = kc >> 2, kb = kc & 3;
            u32 ahr[4], alr[4], bh[4], bl[4];
            ldmA128(ahr, S + oAH, pm0, lane, kc);
            ldmA128(alr, S + oAL, pm0, lane, kc);
            ldmBh(bh, S + oBR + half * 4096, Gp * 16, lane, kb);
            ldmBh(bl, S + oBR + 16384 + half * 4096, Gp * 16, lane, kb);
            mmaf(a4[0], ahr, bh);  mmaf(a4[1], ahr, bh + 2);
            mmaf(a4[0], ahr, bl);  mmaf(a4[1], ahr, bl + 2);
            mmaf(a4[0], alr, bh);  mmaf(a4[1], alr, bh + 2);
        }
        const int lr = lane >> 2, lc = 2 * (lane & 3);
#pragma unroll
        for (int f = 0; f < 2; f++)
#pragma unroll
            for (int i = 0; i < 4; i++) {
                int row = pm0 + lr + (i >> 1) * 8;
                int col = Gp * 16 + f * 8 + lc + (i & 1);
                *(float*)(dsm + oAXH + (row * 32 + col) * 4) = a4[f][i] + __ldg(h2ob + col);
            }
    }
    __syncthreads();

    stageBh(S + oBR,         whT,                 128, tid, 256);
    stageBh(S + oBR + 16384, whT + 16384,         128, tid, 256);
    stageBh(S + oBZ,         whT + 32768,         128, tid, 256);
    stageBh(S + oBZ + 16384, whT + 32768 + 16384, 128, tid, 256);
    cpcommit();

    float v[32];
    const bool act = (tid < 64);
    if (act) {
        const float* pr = (const float*)(dsm + oAXH + tid * 128);
#pragma unroll
        for (int i = 0; i < 32; i++) v[i] = pr[i];
    }
    __syncthreads();
    if (act) {
        const int row = tid;
        float mx = -1e30f;
#pragma unroll
        for (int i = 0; i < 32; i++) mx = fmaxf(mx, v[i]);
        float e[32], sum = 0.0f;
#pragma unroll
        for (int i = 0; i < 32; i++) { e[i] = __expf(v[i] - mx); sum += e[i]; }
        float inv = __fdividef(1.0f, sum);
        size_t go = (size_t)(row0 + row) * 32;
        float4* pg = (float4*)(pred + go);
#pragma unroll
        for (int q = 0; q < 8; q++)
            pg[q] = make_float4(v[4 * q], v[4 * q + 1], v[4 * q + 2], v[4 * q + 3]);
#pragma unroll
        for (int j = 0; j < 16; j++) {
            float p0 = e[2 * j] * inv, p1 = e[2 * j + 1] * inv;
            __half H0, L0, H1, L1;
            wsplit(p0, H0, L0); wsplit(p1, H1, L1);
            __half2 hh2 = __halves2half2(H0, H1), ll2 = __halves2half2(L0, L1);
            *(__half2*)(ph + go + 2 * j) = hh2;
            *(__half2*)(pl + go + 2 * j) = ll2;
            int k = 2 * j;
            u32 xa = (u32)row * 64u + (u32)((((k >> 3) ^ (row & 3)) << 4)) + (k & 7) * 2;
            *(__half2*)(dsm + oAXH + xa) = hh2;
            *(__half2*)(dsm + oAXL + xa) = ll2;
        }
    }
    __syncthreads();

    float acc[8][4];
    gru_body(dsm, S, whT, wiT, tid, lane, m0, n0, acc);

    const int lr = lane >> 2, lc = 2 * (lane & 3);
#pragma unroll
    for (int f = 0; f < 8; f++) {
        int colb = n0 + (f & 3) * 8 + lc;
#pragma unroll
        for (int hp = 0; hp < 2; hp++) {
            int row = m0 + (f >> 2) * 16 + lr + hp * 8;
            __half H0, L0, H1, L1;
            wsplit(acc[f][hp * 2], H0, L0); wsplit(acc[f][hp * 2 + 1], H1, L1);
            size_t go = (size_t)(row0 + row) * 128 + colb;
            *(__half2*)(oh + go) = __halves2half2(H0, H1);
            *(__half2*)(ol + go) = __halves2half2(L0, L1);
        }
    }
}

// ===================== batched grucomb =====================
__global__ __launch_bounds__(256, 2)
void grucomb_b(const __half* __restrict__ whT, const __half* __restrict__ wiT,
               const float* __restrict__ bi, const float* __restrict__ bhp,
               const __half* __restrict__ ufT, const __half* __restrict__ uaT,
               const float* __restrict__ ufb, const float* __restrict__ uab,
               __half* __restrict__ hAh, __half* __restrict__ hAl,
               const __half* __restrict__ prh, const __half* __restrict__ prl,
               Gc lst)
{
    extern __shared__ char dsm[];
    const u32 S = smaddr(dsm);
    const int tid = threadIdx.x, lane = tid & 31, wid = tid >> 5;
    const int slot = blockIdx.x >> 9;
    const int row0 = (blockIdx.x & 511) * 64;
    const int m0 = (wid & 1) * 32, n0 = (wid >> 1) * 32;

    const int idp = lst.p[slot], id1 = lst.l[slot], id2 = lst.r[slot];
    const __half* xh = prh + (size_t)id1 * PP;
    const __half* xl = prl + (size_t)id1 * PP;
    const __half* hh = hAh + (size_t)id1 * PL;
    const __half* hl = hAl + (size_t)id1 * PL;
    const __half* pah = hAh + (size_t)idp * PL;
    const __half* pal = hAl + (size_t)idp * PL;
    __half* oh = hAh + (size_t)id2 * PL;
    __half* ol = hAl + (size_t)id2 * PL;

    load_bias(dsm, bi, bhp, tid);
    stage128(S + oAH, hh + (size_t)row0 * 128, 64, tid, 256);
    stage128(S + oAL, hl + (size_t)row0 * 128, 64, tid, 256);
    stage32s(S + oAXH, xh + (size_t)row0 * 32, 64, tid, 256);
    stage32s(S + oAXL, xl + (size_t)row0 * 32, 64, tid, 256);
    stageBh(S + oBR,         whT,                 128, tid, 256);
    stageBh(S + oBR + 16384, whT + 16384,         128, tid, 256);
    stageBh(S + oBZ,         whT + 32768,         128, tid, 256);
    stageBh(S + oBZ + 16384, whT + 32768 + 16384, 128, tid, 256);
    cpcommit();

    float acc[8][4];
    gru_body(dsm, S, whT, wiT, tid, lane, m0, n0, acc);

    __syncthreads();

    stageBh(S + oBR,         ufT,                 128, tid, 256);
    stageBh(S + oBR + 16384, ufT + 16384,         128, tid, 256);
    stageBh(S + oBZ,         ufT + 64,            128, tid, 256);
    stageBh(S + oBZ + 16384, ufT + 16384 + 64,    128, tid, 256);
    cpcommit();

    const int lr = lane >> 2, lc = 2 * (lane & 3);
#pragma unroll
    for (int f = 0; f < 8; f++) {
        int colb = n0 + (f & 3) * 8 + lc;
#pragma unroll
        for (int hp = 0; hp < 2; hp++) {
            int row = m0 + (f >> 2) * 16 + lr + hp * 8;
            __half H0, L0, H1, L1;
            wsplit(acc[f][hp * 2], H0, L0); wsplit(acc[f][hp * 2 + 1], H1, L1);
            u32 aoff = (u32)row * 256u + (u32)((((colb >> 3) ^ (row & 7)) << 4)) + (colb & 7) * 2;
            *(__half2*)(dsm + oAH + aoff) = __halves2half2(H0, H1);
            *(__half2*)(dsm + oAL + aoff) = __halves2half2(L0, L1);
        }
    }
    cpwait0(); __syncthreads();

    zacc8(acc);
    for (int kc = 0; kc < 4; kc++)
        kstep128h(acc, S + oAH, S + oAL, S + oBR, S + oBR + 16384, m0, n0, lane, kc, kc);
    __syncthreads();
    stageBh(S + oBR,         uaT,         128, tid, 256);
    stageBh(S + oBR + 16384, uaT + 16384, 128, tid, 256);
    cpcommit();
    for (int kc = 4; kc < 8; kc++)
        kstep128h(acc, S + oAH, S + oAL, S + oBZ, S + oBZ + 16384, m0, n0, lane, kc, kc - 4);
    __syncthreads();
    stage128(S + oAH, pah + (size_t)row0 * 128, 64, tid, 256);
    stage128(S + oAL, pal + (size_t)row0 * 128, 64, tid, 256);
    stageBh(S + oBZ,         uaT + 64,         128, tid, 256);
    stageBh(S + oBZ + 16384, uaT + 16384 + 64, 128, tid, 256);
    cpcommit(); cpwait0(); __syncthreads();

    for (int kc = 0; kc < 4; kc++)
        kstep128h(acc, S + oAH, S + oAL, S + oBR, S + oBR + 16384, m0, n0, lane, kc, kc);
    for (int kc = 4; kc < 8; kc++)
        kstep128h(acc, S + oAH, S + oAL, S + oBZ, S + oBZ + 16384, m0, n0, lane, kc, kc - 4);

#pragma unroll
    for (int f = 0; f < 8; f++) {
        int colb = n0 + (f & 3) * 8 + lc;
        float b0 = __ldg(ufb + colb) + __ldg(uab + colb);
        float b1 = __ldg(ufb + colb + 1) + __ldg(uab + colb + 1);
#pragma unroll
        for (int hp = 0; hp < 2; hp++) {
            int row = m0 + (f >> 2) * 16 + lr + hp * 8;
            float o0 = ftanh(acc[f][hp * 2] + b0);
            float o1 = ftanh(acc[f][hp * 2 + 1] + b1);
            __half H0, L0, H1, L1;
            wsplit(o0, H0, L0); wsplit(o1, H1, L1);
            size_t go = (size_t)(row0 + row) * 128 + colb;
            *(__half2*)(oh + go) = __halves2half2(H0, H1);
            *(__half2*)(ol + go) = __halves2half2(L0, L1);
        }
    }
}

// ===================== batched leaf node =====================
#define nAH 0
#define nAL 16384
#define nBH 32768
#define nBL 40960
#define nPR 49152
#define NODE_DS 57344

__global__ __launch_bounds__(256, 2)
void node_b(const __half* __restrict__ h2oT, const float* __restrict__ b,
            float* __restrict__ out,
            const __half* __restrict__ hAh, const __half* __restrict__ hAl,
            __half* __restrict__ prh, __half* __restrict__ prl,
            Ids lst)
{
    extern __shared__ char dsm[];
    const u32 S = smaddr(dsm);
    const int tid = threadIdx.x, lane = tid & 31, wid = tid >> 5;
    const int id = lst.v[blockIdx.x >> 9];
    const int row0 = (blockIdx.x & 511) * 64;

    const __half* hh = hAh + (size_t)id * PL;
    const __half* hl = hAl + (size_t)id * PL;
    float* pred = out + (size_t)id * PP;
    __half* ph = prh + (size_t)id * PP;
    __half* pl = prl + (size_t)id * PP;

    stage128(S + nAH, hh + (size_t)row0 * 128, 64, tid, 256);
    stage128(S + nAL, hl + (size_t)row0 * 128, 64, tid, 256);
    stageBh(S + nBH, h2oT, 32, tid, 256);
    stageBh(S + nBH + 4096, h2oT + 64, 32, tid, 256);
    stageBh(S + nBL, h2oT + 4096, 32, tid, 256);
    stageBh(S + nBL + 4096, h2oT + 4096 + 64, 32, tid, 256);
    cpcommit(); cpwait0(); __syncthreads();

    {
        const int pm0 = (wid & 3) * 16, Gp = wid >> 2;
        float a4[2][4];
#pragma unroll
        for (int f = 0; f < 2; f++)
#pragma unroll
            for (int i = 0; i < 4; i++) a4[f][i] = 0.0f;
        for (int kc = 0; kc < 8; kc++) {
            int half = kc >> 2, kb = kc & 3;
            u32 ahr[4], alr[4], bh[4], bl[4];
            ldmA128(ahr, S + nAH, pm0, lane, kc);
            ldmA128(alr, S + nAL, pm0, lane, kc);
            ldmBh(bh, S + nBH + half * 4096, Gp * 16, lane, kb);
            ldmBh(bl, S + nBL + half * 4096, Gp * 16, lane, kb);
            mmaf(a4[0], ahr, bh);  mmaf(a4[1], ahr, bh + 2);
            mmaf(a4[0], ahr, bl);  mmaf(a4[1], ahr, bl + 2);
            mmaf(a4[0], alr, bh);  mmaf(a4[1], alr, bh + 2);
        }
        const int lr = lane >> 2, lc = 2 * (lane & 3);
#pragma unroll
        for (int f = 0; f < 2; f++)
#pragma unroll
            for (int i = 0; i < 4; i++) {
                int row = pm0 + lr + (i >> 1) * 8;
                int col = Gp * 16 + f * 8 + lc + (i & 1);
                *(float*)(dsm + nPR + (row * 32 + col) * 4) = a4[f][i] + __ldg(b + col);
            }
    }
    __syncthreads();
    if (tid < 64) {
        int row = tid;
        const float* pr = (const float*)(dsm + nPR + row * 128);
        float v[32], mx = -1e30f;
#pragma unroll
        for (int i = 0; i < 32; i++) { v[i] = pr[i]; mx = fmaxf(mx, v[i]); }
        float e[32], sum = 0.0f;
#pragma unroll
        for (int i = 0; i < 32; i++) { e[i] = __expf(v[i] - mx); sum += e[i]; }
        float inv = __fdividef(1.0f, sum);
        size_t go = (size_t)(row0 + row) * 32;
        float4* pg = (float4*)(pred + go);
#pragma unroll
        for (int q = 0; q < 8; q++)
            pg[q] = make_float4(v[4 * q], v[4 * q + 1], v[4 * q + 2], v[4 * q + 3]);
#pragma unroll
        for (int j = 0; j < 16; j++) {
            float p0 = e[2 * j] * inv, p1 = e[2 * j + 1] * inv;
            __half H0, L0, H1, L1;
            wsplit(p0, H0, L0); wsplit(p1, H1, L1);
            *(__half2*)(ph + go + 2 * j) = __halves2half2(H0, H1);
            *(__half2*)(pl + go + 2 * j) = __halves2half2(L0, L1);
        }
    }
}

// ===================== host: wave-batched schedule, single stream =====================
namespace {

static const int SZT[6] = {1, 3, 7, 15, 31, 63};

static int igCnt[NW], lfCnt[NW], gcCnt[NW];
static Ids igT[NW], lfT[NW];
static Gc  gcT[NW];
static bool tblBuilt = false;

void buildTbl(int id, int d, int w)
{
    if (d == DEPTH) { lfT[w].v[lfCnt[w]++] = id; return; }
    igT[w].v[igCnt[w]++] = id;
    int id1 = id + 1;
    int id2 = id + 1 + SZT[DEPTH - d - 1];
    buildTbl(id1, d + 1, w + 1);
    int wg = w + 2;
    gcT[wg].p[gcCnt[wg]] = id;
    gcT[wg].l[gcCnt[wg]] = id1;
    gcT[wg].r[gcCnt[wg]] = id2;
    gcCnt[wg]++;
    buildTbl(id2, d + 1, w + 2);
}

} // namespace

extern "C" void kernel_launch(void* const* d_in, const int* in_sizes, int n_in,
                              void* d_out, int out_size)
{
    const float* z       = (const float*)d_in[0];
    const float* z2h_w   = (const float*)d_in[1];
    const float* z2h_b   = (const float*)d_in[2];
    const float* h2o_w   = (const float*)d_in[3];
    const float* h2o_b   = (const float*)d_in[4];
    const float* anc_wi  = (const float*)d_in[5];
    const float* anc_wh  = (const float*)d_in[6];
    const float* anc_bi  = (const float*)d_in[7];
    const float* anc_bh  = (const float*)d_in[8];
    const float* frat_wi = (const float*)d_in[9];
    const float* frat_wh = (const float*)d_in[10];
    const float* frat_bi = (const float*)d_in[11];
    const float* frat_bh = (const float*)d_in[12];
    const float* ua_w    = (const float*)d_in[13];
    const float* ua_b    = (const float*)d_in[14];
    const float* uf_w    = (const float*)d_in[15];
    const float* uf_b    = (const float*)d_in[16];

    if (!tblBuilt) {
        buildTbl(0, 0, 0);
        cudaFuncSetAttribute(nodegru_b, cudaFuncAttributeMaxDynamicSharedMemorySize, FUSE_DS);
        cudaFuncSetAttribute(grucomb_b, cudaFuncAttributeMaxDynamicSharedMemorySize, FUSE_DS);
        cudaFuncSetAttribute(node_b,    cudaFuncAttributeMaxDynamicSharedMemorySize, NODE_DS);
        tblBuilt = true;
    }

    __half *wt, *hAh, *hAl, *prh, *prl;
    cudaGetSymbolAddress((void**)&wt, g_wt);
    cudaGetSymbolAddress((void**)&hAh, g_hAh);
    cudaGetSymbolAddress((void**)&hAl, g_hAl);
    cudaGetSymbolAddress((void**)&prh, g_prh);
    cudaGetSymbolAddress((void**)&prl, g_prl);

    k_prep<<<128, 256>>>(anc_wi, anc_wh, frat_wi, frat_wh, uf_w, ua_w, h2o_w);
    init_k<<<BATCH / 16, 128>>>(z, z2h_w, z2h_b, hAh, hAl);   // node-0 hidden

    float* out = (float*)d_out;

    for (int w = 0; w < NW; w++) {
        if (gcCnt[w])
            grucomb_b<<<gcCnt[w] * 512, 256, FUSE_DS>>>(
                wt + W_FRAT_WH, wt + W_FRAT_WI, frat_bi, frat_bh,
                wt + W_UF, wt + W_UA, uf_b, ua_b,
                hAh, hAl, prh, prl, gcT[w]);
        if (igCnt[w])
            nodegru_b<<<igCnt[w] * 512, 256, FUSE_DS>>>(
                wt + W_H2O, h2o_b, out,
                wt + W_ANC_WH, wt + W_ANC_WI, anc_bi, anc_bh,
                hAh, hAl, prh, prl, igT[w]);
        if (lfCnt[w])
            node_b<<<lfCnt[w] * 512, 256, NODE_DS>>>(
                wt + W_H2O, h2o_b, out,
                hAh, hAl, prh, prl, lfT[w]);
    }
}